// round 5
// baseline (speedup 1.0000x reference)
#include <cuda_runtime.h>
#include <math.h>

#define N_NODES  50000
#define N_EDGES  800000
#define E_TOT    (N_EDGES + N_NODES)
#define FDIM     128
#define HEADS    4
#define DHEAD    32
#define N_GRAPHS 256
#define NCLS     10
#define BN_EPS   1e-5f
#define NEG_SLOPE 0.2f

#define GF_RELU  1
#define GF_ALPHA 2
#define GF_STATS 4

// ---------------- scratch (device globals; no allocation) ----------------
__device__ float    d_h[N_NODES * FDIM];
__device__ float    d_hw[N_NODES * FDIM];
__device__ float    d_acc[N_NODES * FDIM];
__device__ float    d_eexp[E_TOT * HEADS];
__device__ float    d_als[N_NODES * HEADS];
__device__ float    d_ald[N_NODES * HEADS];
__device__ float    d_esum[N_NODES * HEADS];
__device__ unsigned d_emax[N_NODES * HEADS];
__device__ float    d_stats[2 * FDIM];
__device__ float    d_wp[FDIM * FDIM];
__device__ float    d_bp[FDIM];
__device__ float    d_g[N_GRAPHS * FDIM];

// ---------------- helpers ----------------
__device__ __forceinline__ unsigned fkey(float f) {
    unsigned b = __float_as_uint(f);
    return (b & 0x80000000u) ? ~b : (b | 0x80000000u);
}
__device__ __forceinline__ float funkey(unsigned k) {
    unsigned b = (k & 0x80000000u) ? (k ^ 0x80000000u) : ~k;
    return __uint_as_float(b);
}
__device__ __forceinline__ float lrelu(float x) { return x > 0.f ? x : NEG_SLOPE * x; }

// ---------------- init ----------------
__global__ void zero_small_kernel() {
    int i = blockIdx.x * blockDim.x + threadIdx.x;
    if (i < 2 * FDIM) d_stats[i] = 0.f;
    if (i < N_GRAPHS * FDIM) d_g[i] = 0.f;
}

__global__ void conv_init_kernel() {
    int i = blockIdx.x * blockDim.x + threadIdx.x;   // float4 index
    float4 z = make_float4(0.f, 0.f, 0.f, 0.f);
    if (i < (N_NODES * FDIM) / 4) ((float4*)d_acc)[i] = z;
    if (i < (N_NODES * HEADS) / 4) {
        ((float4*)d_esum)[i] = z;
        ((uint4*)d_emax)[i] = make_uint4(0u, 0u, 0u, 0u);
    }
}

// ---------------- per-column stats of input x ----------------
__global__ void colstats_kernel(const float* __restrict__ A, int rows) {
    int t = threadIdx.x;
    int per = (rows + gridDim.x - 1) / gridDim.x;
    int r0 = blockIdx.x * per;
    int r1 = min(r0 + per, rows);
    float s = 0.f, q = 0.f;
    for (int r = r0; r < r1; r++) {
        float v = A[(size_t)r * FDIM + t];
        s += v; q += v * v;
    }
    atomicAdd(&d_stats[t], s);
    atomicAdd(&d_stats[FDIM + t], q);
}

// stats over pooled graph features (device-global source)
__global__ void colstats_g_kernel() {
    int t = threadIdx.x;
    int per = (N_GRAPHS + gridDim.x - 1) / gridDim.x;
    int r0 = blockIdx.x * per;
    int r1 = min(r0 + per, N_GRAPHS);
    float s = 0.f, q = 0.f;
    for (int r = r0; r < r1; r++) {
        float v = d_g[r * FDIM + t];
        s += v; q += v * v;
    }
    atomicAdd(&d_stats[t], s);
    atomicAdd(&d_stats[FDIM + t], q);
}

// ---------------- fold BN into weight ----------------
__global__ void transform_kernel(const float* __restrict__ W,
                                 const float* __restrict__ g,
                                 const float* __restrict__ b,
                                 const float* __restrict__ extra_bias,
                                 float inv_n) {
    int t = threadIdx.x;
    __shared__ float sc[FDIM], sh[FDIM];
    float mean = d_stats[t] * inv_n;
    float var  = d_stats[FDIM + t] * inv_n - mean * mean;
    float s = g[t] * rsqrtf(var + BN_EPS);
    sc[t] = s;
    sh[t] = b[t] - mean * s;
    d_stats[t] = 0.f;
    d_stats[FDIM + t] = 0.f;
    __syncthreads();
    float bp = extra_bias ? extra_bias[t] : 0.f;
    for (int k = 0; k < FDIM; k++) {
        float w = W[k * FDIM + t];
        d_wp[k * FDIM + t] = sc[k] * w;
        bp += sh[k] * w;
    }
    d_bp[t] = bp;
}

// ---------------- main GEMM with fused epilogues ----------------
__global__ void __launch_bounds__(256, 2)
gemm_kernel(const float* __restrict__ Aext, int asel, int M, int csel,
            const float* __restrict__ a_src, const float* __restrict__ a_dst,
            int flags) {
    __shared__ float Ws[32 * 128];
    __shared__ float sred[256];
    const float* A = (asel == 0) ? Aext
                    : (asel == 1 ? (const float*)d_h : (const float*)d_g);
    float* C = (csel == 1) ? (float*)d_h : (float*)d_hw;

    int tid = threadIdx.x;
    int tx = tid & 31, ty = tid >> 5;
    int row0 = blockIdx.x * 64 + ty * 8;

    const float4* pA[8];
#pragma unroll
    for (int r = 0; r < 8; r++) {
        int row = row0 + r; if (row >= M) row = M - 1;
        pA[r] = (const float4*)(A + (size_t)row * FDIM);
    }
    float acc[8][4];
#pragma unroll
    for (int r = 0; r < 8; r++) { acc[r][0] = acc[r][1] = acc[r][2] = acc[r][3] = 0.f; }

    for (int kt = 0; kt < 128; kt += 32) {
#pragma unroll
        for (int i = 0; i < 4; i++) {
            int idx = tid + i * 256;
            ((float4*)Ws)[idx] = ((const float4*)(d_wp + kt * 128))[idx];
        }
        __syncthreads();
#pragma unroll
        for (int k = 0; k < 32; k += 4) {
            float4 w0 = *(float4*)&Ws[(k + 0) * 128 + 4 * tx];
            float4 w1 = *(float4*)&Ws[(k + 1) * 128 + 4 * tx];
            float4 w2 = *(float4*)&Ws[(k + 2) * 128 + 4 * tx];
            float4 w3 = *(float4*)&Ws[(k + 3) * 128 + 4 * tx];
#pragma unroll
            for (int r = 0; r < 8; r++) {
                float4 a = __ldg(&pA[r][(kt + k) >> 2]);
                acc[r][0] += a.x * w0.x + a.y * w1.x + a.z * w2.x + a.w * w3.x;
                acc[r][1] += a.x * w0.y + a.y * w1.y + a.z * w2.y + a.w * w3.y;
                acc[r][2] += a.x * w0.z + a.y * w1.z + a.z * w2.z + a.w * w3.z;
                acc[r][3] += a.x * w0.w + a.y * w1.w + a.z * w2.w + a.w * w3.w;
            }
        }
        __syncthreads();
    }

    float4 bp4 = *(const float4*)&d_bp[4 * tx];
    int head = tx >> 3;
    float4 av_s = make_float4(0, 0, 0, 0), av_d = make_float4(0, 0, 0, 0);
    if (flags & GF_ALPHA) {
        av_s = *(const float4*)&a_src[head * DHEAD + 4 * (tx & 7)];
        av_d = *(const float4*)&a_dst[head * DHEAD + 4 * (tx & 7)];
    }
    float ss0 = 0, ss1 = 0, ss2 = 0, ss3 = 0;
    float sq0 = 0, sq1 = 0, sq2 = 0, sq3 = 0;
#pragma unroll
    for (int r = 0; r < 8; r++) {
        int row = row0 + r;
        if (row >= M) break;                        // uniform per warp
        float4 v;
        v.x = acc[r][0] + bp4.x; v.y = acc[r][1] + bp4.y;
        v.z = acc[r][2] + bp4.z; v.w = acc[r][3] + bp4.w;
        if (flags & GF_ALPHA) {
            float ps = v.x * av_s.x + v.y * av_s.y + v.z * av_s.z + v.w * av_s.w;
            float pd = v.x * av_d.x + v.y * av_d.y + v.z * av_d.z + v.w * av_d.w;
#pragma unroll
            for (int off = 4; off > 0; off >>= 1) {
                ps += __shfl_down_sync(0xffffffffu, ps, off, 8);
                pd += __shfl_down_sync(0xffffffffu, pd, off, 8);
            }
            if ((tx & 7) == 0) {
                d_als[row * HEADS + head] = ps;
                d_ald[row * HEADS + head] = pd;
            }
        }
        if (flags & GF_RELU) {
            v.x = fmaxf(v.x, 0.f); v.y = fmaxf(v.y, 0.f);
            v.z = fmaxf(v.z, 0.f); v.w = fmaxf(v.w, 0.f);
        }
        *(float4*)&C[(size_t)row * FDIM + 4 * tx] = v;
        ss0 += v.x; ss1 += v.y; ss2 += v.z; ss3 += v.w;
        sq0 += v.x * v.x; sq1 += v.y * v.y; sq2 += v.z * v.z; sq3 += v.w * v.w;
    }
    if (flags & GF_STATS) {
        sred[tid] = 0.f;
        __syncthreads();
        atomicAdd(&sred[4 * tx + 0], ss0); atomicAdd(&sred[4 * tx + 1], ss1);
        atomicAdd(&sred[4 * tx + 2], ss2); atomicAdd(&sred[4 * tx + 3], ss3);
        atomicAdd(&sred[128 + 4 * tx + 0], sq0); atomicAdd(&sred[128 + 4 * tx + 1], sq1);
        atomicAdd(&sred[128 + 4 * tx + 2], sq2); atomicAdd(&sred[128 + 4 * tx + 3], sq3);
        __syncthreads();
        atomicAdd(&d_stats[tid], sred[tid]);
    }
}

// ---------------- edge pass 1: logits + segment max ----------------
__global__ void edge_logits_kernel(const int* __restrict__ esrc,
                                   const int* __restrict__ edst) {
    int e = blockIdx.x * blockDim.x + threadIdx.x;
    if (e >= E_TOT) return;
    int s, d;
    if (e < N_EDGES) { s = esrc[e]; d = edst[e]; } else { s = d = e - N_EDGES; }
    float4 as = *(const float4*)&d_als[s * HEADS];
    float4 ad = *(const float4*)&d_ald[d * HEADS];
    float4 l;
    l.x = lrelu(as.x + ad.x); l.y = lrelu(as.y + ad.y);
    l.z = lrelu(as.z + ad.z); l.w = lrelu(as.w + ad.w);
    *(float4*)&d_eexp[e * HEADS] = l;
    atomicMax(&d_emax[d * HEADS + 0], fkey(l.x));
    atomicMax(&d_emax[d * HEADS + 1], fkey(l.y));
    atomicMax(&d_emax[d * HEADS + 2], fkey(l.z));
    atomicMax(&d_emax[d * HEADS + 3], fkey(l.w));
}

// ---------------- edge pass 2: exp + segment sum ----------------
__global__ void edge_expsum_kernel(const int* __restrict__ edst) {
    int e = blockIdx.x * blockDim.x + threadIdx.x;
    if (e >= E_TOT) return;
    int d = (e < N_EDGES) ? edst[e] : e - N_EDGES;
    float4 l = *(const float4*)&d_eexp[e * HEADS];
    float4 ex;
    ex.x = __expf(l.x - funkey(d_emax[d * HEADS + 0]));
    ex.y = __expf(l.y - funkey(d_emax[d * HEADS + 1]));
    ex.z = __expf(l.z - funkey(d_emax[d * HEADS + 2]));
    ex.w = __expf(l.w - funkey(d_emax[d * HEADS + 3]));
    *(float4*)&d_eexp[e * HEADS] = ex;
    atomicAdd(&d_esum[d * HEADS + 0], ex.x);
    atomicAdd(&d_esum[d * HEADS + 1], ex.y);
    atomicAdd(&d_esum[d * HEADS + 2], ex.z);
    atomicAdd(&d_esum[d * HEADS + 3], ex.w);
}

// ---------------- edge pass 3: warp-per-edge scatter ----------------
__global__ void edge_scatter_kernel(const int* __restrict__ esrc,
                                    const int* __restrict__ edst) {
    int gt = blockIdx.x * blockDim.x + threadIdx.x;
    int e = gt >> 5;
    if (e >= E_TOT) return;
    int lane = gt & 31;
    int s, d;
    if (e < N_EDGES) { s = esrc[e]; d = edst[e]; } else { s = d = e - N_EDGES; }
    int head = lane >> 3;
    float ex = d_eexp[e * HEADS + head];
    float sm = d_esum[d * HEADS + head];
    float alpha = ex / (sm + 1e-16f);
    float4 hv = *(const float4*)&d_hw[(size_t)s * FDIM + lane * 4];
    float4 m = make_float4(hv.x * alpha, hv.y * alpha, hv.z * alpha, hv.w * alpha);
    atomicAdd((float4*)&d_acc[(size_t)d * FDIM + lane * 4], m);
}

// ---------------- GAT epilogue ----------------
__global__ void node_epilogue_kernel(const float* __restrict__ bias, int do_stats) {
    int t = threadIdx.x;
    int per = (N_NODES + gridDim.x - 1) / gridDim.x;
    int r0 = blockIdx.x * per;
    int r1 = min(r0 + per, N_NODES);
    float bv = bias[t];
    float s = 0.f, q = 0.f;
    for (int r = r0; r < r1; r++) {
        float v = fmaxf(d_acc[(size_t)r * FDIM + t] + bv, 0.f);
        d_h[(size_t)r * FDIM + t] = v;
        s += v; q += v * v;
    }
    if (do_stats) {
        atomicAdd(&d_stats[t], s);
        atomicAdd(&d_stats[FDIM + t], q);
    }
}

// ---------------- global add pool ----------------
__global__ void pool_kernel(const int* __restrict__ batch) {
    int gt = blockIdx.x * blockDim.x + threadIdx.x;
    int n = gt >> 5;
    if (n >= N_NODES) return;
    int lane = gt & 31;
    int gi = batch[n];
    float4 v = *(const float4*)&d_h[(size_t)n * FDIM + lane * 4];
    atomicAdd((float4*)&d_g[gi * FDIM + lane * 4], v);
}

// ---------------- BN(g2) + classifier + log_softmax ----------------
__global__ void classifier_kernel(const float* __restrict__ bnh_g,
                                  const float* __restrict__ bnh_b,
                                  const float* __restrict__ cls_w,
                                  const float* __restrict__ cls_b,
                                  float* __restrict__ out) {
    int gi = blockIdx.x, t = threadIdx.x;
    float mean = d_stats[t] * (1.0f / N_GRAPHS);
    float var  = d_stats[FDIM + t] * (1.0f / N_GRAPHS) - mean * mean;
    float v = (d_hw[gi * FDIM + t] - mean) * rsqrtf(var + BN_EPS) * bnh_g[t] + bnh_b[t];
    __shared__ float sh[128];
    __shared__ float z[16];
    for (int c = 0; c < NCLS; c++) {
        sh[t] = v * cls_w[t * NCLS + c];
        __syncthreads();
        if (t < 64) sh[t] += sh[t + 64];
        __syncthreads();
        if (t < 32) {
            float s = sh[t] + sh[t + 32];
#pragma unroll
            for (int off = 16; off > 0; off >>= 1)
                s += __shfl_down_sync(0xffffffffu, s, off);
            if (t == 0) z[c] = s + cls_b[c];
        }
        __syncthreads();
    }
    if (t == 0) {
        float m = z[0];
        for (int c = 1; c < NCLS; c++) m = fmaxf(m, z[c]);
        float se = 0.f;
        for (int c = 0; c < NCLS; c++) se += expf(z[c] - m);
        float lse = m + logf(se);
        for (int c = 0; c < NCLS; c++) out[gi * NCLS + c] = z[c] - lse;
    }
}

// ---------------- launch ----------------
extern "C" void kernel_launch(void* const* d_in, const int* in_sizes, int n_in,
                              void* d_out, int out_size) {
    const float* x        = (const float*)d_in[0];
    const int*   eidx     = (const int*)d_in[1];
    const int*   batch    = (const int*)d_in[2];
    const float* w_feat   = (const float*)d_in[3];
    const float* bnf_g    = (const float*)d_in[4];
    const float* bnf_b    = (const float*)d_in[5];
    const float* bnc_g    = (const float*)d_in[6];
    const float* bnc_b    = (const float*)d_in[7];
    const float* gat_w    = (const float*)d_in[8];
    const float* gat_asrc = (const float*)d_in[9];
    const float* gat_adst = (const float*)d_in[10];
    const float* gat_b    = (const float*)d_in[11];
    const float* bnfc_g   = (const float*)d_in[12];
    const float* bnfc_b   = (const float*)d_in[13];
    const float* lin_w    = (const float*)d_in[14];
    const float* lin_b    = (const float*)d_in[15];
    const float* bnh_g    = (const float*)d_in[16];
    const float* bnh_b    = (const float*)d_in[17];
    const float* cls_w    = (const float*)d_in[18];
    const float* cls_b    = (const float*)d_in[19];
    float* out = (float*)d_out;

    const int* esrc = eidx;
    const int* edst = eidx + N_EDGES;

    const int gemm_blocks = (N_NODES + 63) / 64;
    const int edge_blocks = (E_TOT + 255) / 256;
    const int scat_blocks = (E_TOT * 32 + 255) / 256;
    const int init_blocks = (N_NODES * FDIM / 4 + 255) / 256;
    const int pool_blocks = (N_NODES * 32 + 255) / 256;

    zero_small_kernel<<<128, 256>>>();
    colstats_kernel<<<200, 128>>>(x, N_NODES);
    transform_kernel<<<1, 128>>>(w_feat, bnf_g, bnf_b, nullptr, 1.0f / N_NODES);
    gemm_kernel<<<gemm_blocks, 256>>>(x, 0, N_NODES, 1, nullptr, nullptr,
                                      GF_RELU | GF_STATS);

    for (int i = 0; i < 3; i++) {
        transform_kernel<<<1, 128>>>(gat_w + i * FDIM * FDIM,
                                     bnc_g + i * FDIM, bnc_b + i * FDIM,
                                     nullptr, 1.0f / N_NODES);
        gemm_kernel<<<gemm_blocks, 256>>>(nullptr, 1, N_NODES, 2,
                                          gat_asrc + i * HEADS * DHEAD,
                                          gat_adst + i * HEADS * DHEAD, GF_ALPHA);
        conv_init_kernel<<<init_blocks, 256>>>();
        edge_logits_kernel<<<edge_blocks, 256>>>(esrc, edst);
        edge_expsum_kernel<<<edge_blocks, 256>>>(edst);
        edge_scatter_kernel<<<scat_blocks, 256>>>(esrc, edst);
        node_epilogue_kernel<<<200, 128>>>(gat_b + i * FDIM, (i < 2) ? 1 : 0);
    }

    pool_kernel<<<pool_blocks, 256>>>(batch);
    colstats_g_kernel<<<8, 128>>>();
    transform_kernel<<<1, 128>>>(lin_w, bnfc_g, bnfc_b, lin_b, 1.0f / N_GRAPHS);
    gemm_kernel<<<(N_GRAPHS + 63) / 64, 256>>>(nullptr, 2, N_GRAPHS, 2,
                                               nullptr, nullptr, GF_RELU | GF_STATS);
    classifier_kernel<<<N_GRAPHS, 128>>>(bnh_g, bnh_b, cls_w, cls_b, out);
}

// round 6
// speedup vs baseline: 1.9380x; 1.9380x over previous
#include <cuda_runtime.h>
#include <math.h>

#define N_NODES  50000
#define N_EDGES  800000
#define FDIM     128
#define HEADS    4
#define DHEAD    32
#define N_GRAPHS 256
#define NCLS     10
#define BN_EPS   1e-5f
#define NEG_SLOPE 0.2f

#define GF_RELU  1
#define GF_ALPHA 2
#define GF_STATS 4

// ---------------- scratch (device globals; no allocation) ----------------
__device__ float d_h[N_NODES * FDIM];
__device__ float d_hw[N_NODES * FDIM];
__device__ float d_als[N_NODES * HEADS];
__device__ float d_ald[N_NODES * HEADS];
__device__ float d_stats[2 * FDIM];
__device__ float d_wp[FDIM * FDIM];
__device__ float d_bp[FDIM];
__device__ float d_g[N_GRAPHS * FDIM];
// CSR (built once per launch, reused for all 3 convs)
__device__ int   d_deg[N_NODES];
__device__ int   d_start[N_NODES + 1];
__device__ int   d_cursor[N_NODES];
__device__ int   d_ssrc[N_EDGES];
__device__ int   d_partial[256];

__device__ __forceinline__ float lrelu(float x) { return x > 0.f ? x : NEG_SLOPE * x; }

// ---------------- init ----------------
__global__ void zero_small_kernel() {
    int i = blockIdx.x * blockDim.x + threadIdx.x;
    if (i < 2 * FDIM) d_stats[i] = 0.f;
    if (i < N_GRAPHS * FDIM) d_g[i] = 0.f;
    if (i < N_NODES) d_deg[i] = 0;
}

// ---------------- CSR build ----------------
__global__ void csr_count_kernel(const int* __restrict__ edst) {
    int e = blockIdx.x * blockDim.x + threadIdx.x;
    if (e < N_EDGES) atomicAdd(&d_deg[edst[e]], 1);
}

#define SCAN_NB 256
#define SCAN_CHUNK ((N_NODES + SCAN_NB - 1) / SCAN_NB)   // 196

__global__ void scan1_kernel() {
    __shared__ int sred[256];
    int b = blockIdx.x, t = threadIdx.x;
    int idx = b * SCAN_CHUNK + t;
    int v = (t < SCAN_CHUNK && idx < N_NODES) ? d_deg[idx] : 0;
    sred[t] = v;
    __syncthreads();
    for (int off = 128; off > 0; off >>= 1) {
        if (t < off) sred[t] += sred[t + off];
        __syncthreads();
    }
    if (t == 0) d_partial[b] = sred[0];
}

__global__ void scan2_kernel() {
    if (threadIdx.x == 0) {
        int run = 0;
        for (int i = 0; i < SCAN_NB; i++) {
            int v = d_partial[i];
            d_partial[i] = run;
            run += v;
        }
    }
}

__global__ void scan3_kernel() {
    int b = blockIdx.x;
    if (threadIdx.x != 0) return;
    int run = d_partial[b];
    int i0 = b * SCAN_CHUNK;
    int i1 = min(i0 + SCAN_CHUNK, N_NODES);
    for (int i = i0; i < i1; i++) {
        d_start[i] = run;
        d_cursor[i] = run;
        run += d_deg[i];
    }
    if (i1 == N_NODES) d_start[N_NODES] = run;
}

__global__ void csr_scatter_kernel(const int* __restrict__ esrc,
                                   const int* __restrict__ edst) {
    int e = blockIdx.x * blockDim.x + threadIdx.x;
    if (e >= N_EDGES) return;
    int pos = atomicAdd(&d_cursor[edst[e]], 1);
    d_ssrc[pos] = esrc[e];
}

// ---------------- per-column stats ----------------
__global__ void colstats_kernel(const float* __restrict__ A, int rows) {
    int t = threadIdx.x;
    int per = (rows + gridDim.x - 1) / gridDim.x;
    int r0 = blockIdx.x * per;
    int r1 = min(r0 + per, rows);
    float s = 0.f, q = 0.f;
    for (int r = r0; r < r1; r++) {
        float v = A[(size_t)r * FDIM + t];
        s += v; q += v * v;
    }
    atomicAdd(&d_stats[t], s);
    atomicAdd(&d_stats[FDIM + t], q);
}

__global__ void colstats_g_kernel() {
    int t = threadIdx.x;
    int per = (N_GRAPHS + gridDim.x - 1) / gridDim.x;
    int r0 = blockIdx.x * per;
    int r1 = min(r0 + per, N_GRAPHS);
    float s = 0.f, q = 0.f;
    for (int r = r0; r < r1; r++) {
        float v = d_g[r * FDIM + t];
        s += v; q += v * v;
    }
    atomicAdd(&d_stats[t], s);
    atomicAdd(&d_stats[FDIM + t], q);
}

// ---------------- fold BN into weight ----------------
__global__ void transform_kernel(const float* __restrict__ W,
                                 const float* __restrict__ g,
                                 const float* __restrict__ b,
                                 const float* __restrict__ extra_bias,
                                 float inv_n) {
    int t = threadIdx.x;
    __shared__ float sc[FDIM], sh[FDIM];
    float mean = d_stats[t] * inv_n;
    float var  = d_stats[FDIM + t] * inv_n - mean * mean;
    float s = g[t] * rsqrtf(var + BN_EPS);
    sc[t] = s;
    sh[t] = b[t] - mean * s;
    d_stats[t] = 0.f;
    d_stats[FDIM + t] = 0.f;
    __syncthreads();
    float bp = extra_bias ? extra_bias[t] : 0.f;
    for (int k = 0; k < FDIM; k++) {
        float w = W[k * FDIM + t];
        d_wp[k * FDIM + t] = sc[k] * w;
        bp += sh[k] * w;
    }
    d_bp[t] = bp;
}

// ---------------- main GEMM with fused epilogues ----------------
__global__ void __launch_bounds__(256, 2)
gemm_kernel(const float* __restrict__ Aext, int asel, int M, int csel,
            const float* __restrict__ a_src, const float* __restrict__ a_dst,
            int flags) {
    __shared__ float Ws[32 * 128];
    __shared__ float sred[256];
    const float* A = (asel == 0) ? Aext
                    : (asel == 1 ? (const float*)d_h : (const float*)d_g);
    float* C = (csel == 1) ? (float*)d_h : (float*)d_hw;

    int tid = threadIdx.x;
    int tx = tid & 31, ty = tid >> 5;
    int row0 = blockIdx.x * 64 + ty * 8;

    const float4* pA[8];
#pragma unroll
    for (int r = 0; r < 8; r++) {
        int row = row0 + r; if (row >= M) row = M - 1;
        pA[r] = (const float4*)(A + (size_t)row * FDIM);
    }
    float acc[8][4];
#pragma unroll
    for (int r = 0; r < 8; r++) { acc[r][0] = acc[r][1] = acc[r][2] = acc[r][3] = 0.f; }

    for (int kt = 0; kt < 128; kt += 32) {
#pragma unroll
        for (int i = 0; i < 4; i++) {
            int idx = tid + i * 256;
            ((float4*)Ws)[idx] = ((const float4*)(d_wp + kt * 128))[idx];
        }
        __syncthreads();
#pragma unroll
        for (int k = 0; k < 32; k += 4) {
            float4 w0 = *(float4*)&Ws[(k + 0) * 128 + 4 * tx];
            float4 w1 = *(float4*)&Ws[(k + 1) * 128 + 4 * tx];
            float4 w2 = *(float4*)&Ws[(k + 2) * 128 + 4 * tx];
            float4 w3 = *(float4*)&Ws[(k + 3) * 128 + 4 * tx];
#pragma unroll
            for (int r = 0; r < 8; r++) {
                float4 a = __ldg(&pA[r][(kt + k) >> 2]);
                acc[r][0] += a.x * w0.x + a.y * w1.x + a.z * w2.x + a.w * w3.x;
                acc[r][1] += a.x * w0.y + a.y * w1.y + a.z * w2.y + a.w * w3.y;
                acc[r][2] += a.x * w0.z + a.y * w1.z + a.z * w2.z + a.w * w3.z;
                acc[r][3] += a.x * w0.w + a.y * w1.w + a.z * w2.w + a.w * w3.w;
            }
        }
        __syncthreads();
    }

    float4 bp4 = *(const float4*)&d_bp[4 * tx];
    int head = tx >> 3;
    float4 av_s = make_float4(0, 0, 0, 0), av_d = make_float4(0, 0, 0, 0);
    if (flags & GF_ALPHA) {
        av_s = *(const float4*)&a_src[head * DHEAD + 4 * (tx & 7)];
        av_d = *(const float4*)&a_dst[head * DHEAD + 4 * (tx & 7)];
    }
    float ss0 = 0, ss1 = 0, ss2 = 0, ss3 = 0;
    float sq0 = 0, sq1 = 0, sq2 = 0, sq3 = 0;
#pragma unroll
    for (int r = 0; r < 8; r++) {
        int row = row0 + r;
        if (row >= M) break;                        // uniform per warp
        float4 v;
        v.x = acc[r][0] + bp4.x; v.y = acc[r][1] + bp4.y;
        v.z = acc[r][2] + bp4.z; v.w = acc[r][3] + bp4.w;
        if (flags & GF_ALPHA) {
            float ps = v.x * av_s.x + v.y * av_s.y + v.z * av_s.z + v.w * av_s.w;
            float pd = v.x * av_d.x + v.y * av_d.y + v.z * av_d.z + v.w * av_d.w;
#pragma unroll
            for (int off = 4; off > 0; off >>= 1) {
                ps += __shfl_down_sync(0xffffffffu, ps, off, 8);
                pd += __shfl_down_sync(0xffffffffu, pd, off, 8);
            }
            if ((tx & 7) == 0) {
                d_als[row * HEADS + head] = ps;
                d_ald[row * HEADS + head] = pd;
            }
        }
        if (flags & GF_RELU) {
            v.x = fmaxf(v.x, 0.f); v.y = fmaxf(v.y, 0.f);
            v.z = fmaxf(v.z, 0.f); v.w = fmaxf(v.w, 0.f);
        }
        *(float4*)&C[(size_t)row * FDIM + 4 * tx] = v;
        ss0 += v.x; ss1 += v.y; ss2 += v.z; ss3 += v.w;
        sq0 += v.x * v.x; sq1 += v.y * v.y; sq2 += v.z * v.z; sq3 += v.w * v.w;
    }
    if (flags & GF_STATS) {
        sred[tid] = 0.f;
        __syncthreads();
        atomicAdd(&sred[4 * tx + 0], ss0); atomicAdd(&sred[4 * tx + 1], ss1);
        atomicAdd(&sred[4 * tx + 2], ss2); atomicAdd(&sred[4 * tx + 3], ss3);
        atomicAdd(&sred[128 + 4 * tx + 0], sq0); atomicAdd(&sred[128 + 4 * tx + 1], sq1);
        atomicAdd(&sred[128 + 4 * tx + 2], sq2); atomicAdd(&sred[128 + 4 * tx + 3], sq3);
        __syncthreads();
        atomicAdd(&d_stats[tid], sred[tid]);
    }
}

// ---------------- fused GAT aggregation (warp per dst node) ----------------
// softmax shift-invariance: out = (sum_e exp(l_e) * hw[src_e]) / (sum_e exp(l_e) + eps)
// (the segment-max shift cancels exactly; logits are O(1) so no overflow)
__global__ void __launch_bounds__(256)
agg_kernel(const float* __restrict__ bias, int do_stats) {
    __shared__ float sred[256];
    int tid = threadIdx.x;
    int lane = tid & 31;
    int n = blockIdx.x * 8 + (tid >> 5);
    int head = lane >> 3;

    float ss0 = 0, ss1 = 0, ss2 = 0, ss3 = 0;
    float sq0 = 0, sq1 = 0, sq2 = 0, sq3 = 0;

    if (n < N_NODES) {
        float aldv = d_ald[n * HEADS + head];
        // self-loop contribution
        float e = __expf(lrelu(d_als[n * HEADS + head] + aldv));
        float4 hv = *(const float4*)&d_hw[(size_t)n * FDIM + lane * 4];
        float4 acc = make_float4(e * hv.x, e * hv.y, e * hv.z, e * hv.w);
        float S = e;

        int p = d_start[n];
        int pend = d_start[n + 1];
        // one-ahead prefetch of src index + attention term
        int s_nx = 0; float a_nx = 0.f;
        if (p < pend) {
            s_nx = __ldg(&d_ssrc[p]);
            a_nx = __ldg(&d_als[s_nx * HEADS + head]);
        }
        for (; p < pend; p++) {
            int s = s_nx;
            float av = a_nx;
            if (p + 1 < pend) {
                s_nx = __ldg(&d_ssrc[p + 1]);
                a_nx = __ldg(&d_als[s_nx * HEADS + head]);
            }
            float4 h4 = __ldg((const float4*)&d_hw[(size_t)s * FDIM + lane * 4]);
            float ee = __expf(lrelu(av + aldv));
            S += ee;
            acc.x += ee * h4.x; acc.y += ee * h4.y;
            acc.z += ee * h4.z; acc.w += ee * h4.w;
        }
        float inv = 1.0f / (S + 1e-16f);
        float4 bv = *(const float4*)&bias[lane * 4];
        float4 v;
        v.x = fmaxf(acc.x * inv + bv.x, 0.f);
        v.y = fmaxf(acc.y * inv + bv.y, 0.f);
        v.z = fmaxf(acc.z * inv + bv.z, 0.f);
        v.w = fmaxf(acc.w * inv + bv.w, 0.f);
        *(float4*)&d_h[(size_t)n * FDIM + lane * 4] = v;
        ss0 = v.x; ss1 = v.y; ss2 = v.z; ss3 = v.w;
        sq0 = v.x * v.x; sq1 = v.y * v.y; sq2 = v.z * v.z; sq3 = v.w * v.w;
    }

    if (do_stats) {
        sred[tid] = 0.f;
        __syncthreads();
        atomicAdd(&sred[4 * lane + 0], ss0); atomicAdd(&sred[4 * lane + 1], ss1);
        atomicAdd(&sred[4 * lane + 2], ss2); atomicAdd(&sred[4 * lane + 3], ss3);
        atomicAdd(&sred[128 + 4 * lane + 0], sq0); atomicAdd(&sred[128 + 4 * lane + 1], sq1);
        atomicAdd(&sred[128 + 4 * lane + 2], sq2); atomicAdd(&sred[128 + 4 * lane + 3], sq3);
        __syncthreads();
        atomicAdd(&d_stats[tid], sred[tid]);
    }
}

// ---------------- global add pool ----------------
__global__ void pool_kernel(const int* __restrict__ batch) {
    int gt = blockIdx.x * blockDim.x + threadIdx.x;
    int n = gt >> 5;
    if (n >= N_NODES) return;
    int lane = gt & 31;
    int gi = batch[n];
    float4 v = *(const float4*)&d_h[(size_t)n * FDIM + lane * 4];
    atomicAdd((float4*)&d_g[gi * FDIM + lane * 4], v);
}

// ---------------- BN(g2) + classifier + log_softmax ----------------
__global__ void classifier_kernel(const float* __restrict__ bnh_g,
                                  const float* __restrict__ bnh_b,
                                  const float* __restrict__ cls_w,
                                  const float* __restrict__ cls_b,
                                  float* __restrict__ out) {
    int gi = blockIdx.x, t = threadIdx.x;
    float mean = d_stats[t] * (1.0f / N_GRAPHS);
    float var  = d_stats[FDIM + t] * (1.0f / N_GRAPHS) - mean * mean;
    float v = (d_hw[gi * FDIM + t] - mean) * rsqrtf(var + BN_EPS) * bnh_g[t] + bnh_b[t];
    __shared__ float sh[128];
    __shared__ float z[16];
    for (int c = 0; c < NCLS; c++) {
        sh[t] = v * cls_w[t * NCLS + c];
        __syncthreads();
        if (t < 64) sh[t] += sh[t + 64];
        __syncthreads();
        if (t < 32) {
            float s = sh[t] + sh[t + 32];
#pragma unroll
            for (int off = 16; off > 0; off >>= 1)
                s += __shfl_down_sync(0xffffffffu, s, off);
            if (t == 0) z[c] = s + cls_b[c];
        }
        __syncthreads();
    }
    if (t == 0) {
        float m = z[0];
        for (int c = 1; c < NCLS; c++) m = fmaxf(m, z[c]);
        float se = 0.f;
        for (int c = 0; c < NCLS; c++) se += expf(z[c] - m);
        float lse = m + logf(se);
        for (int c = 0; c < NCLS; c++) out[gi * NCLS + c] = z[c] - lse;
    }
}

// ---------------- launch ----------------
extern "C" void kernel_launch(void* const* d_in, const int* in_sizes, int n_in,
                              void* d_out, int out_size) {
    const float* x        = (const float*)d_in[0];
    const int*   eidx     = (const int*)d_in[1];
    const int*   batch    = (const int*)d_in[2];
    const float* w_feat   = (const float*)d_in[3];
    const float* bnf_g    = (const float*)d_in[4];
    const float* bnf_b    = (const float*)d_in[5];
    const float* bnc_g    = (const float*)d_in[6];
    const float* bnc_b    = (const float*)d_in[7];
    const float* gat_w    = (const float*)d_in[8];
    const float* gat_asrc = (const float*)d_in[9];
    const float* gat_adst = (const float*)d_in[10];
    const float* gat_b    = (const float*)d_in[11];
    const float* bnfc_g   = (const float*)d_in[12];
    const float* bnfc_b   = (const float*)d_in[13];
    const float* lin_w    = (const float*)d_in[14];
    const float* lin_b    = (const float*)d_in[15];
    const float* bnh_g    = (const float*)d_in[16];
    const float* bnh_b    = (const float*)d_in[17];
    const float* cls_w    = (const float*)d_in[18];
    const float* cls_b    = (const float*)d_in[19];
    float* out = (float*)d_out;

    const int* esrc = eidx;
    const int* edst = eidx + N_EDGES;

    const int gemm_blocks = (N_NODES + 63) / 64;
    const int edge_blocks = (N_EDGES + 255) / 256;
    const int agg_blocks  = (N_NODES + 7) / 8;
    const int pool_blocks = (N_NODES * 32 + 255) / 256;

    // init + CSR build (reused for all 3 convs)
    zero_small_kernel<<<(N_NODES + 255) / 256, 256>>>();
    csr_count_kernel<<<edge_blocks, 256>>>(edst);
    scan1_kernel<<<SCAN_NB, 256>>>();
    scan2_kernel<<<1, 32>>>();
    scan3_kernel<<<SCAN_NB, 32>>>();
    csr_scatter_kernel<<<edge_blocks, 256>>>(esrc, edst);

    // bn_feat folded into w_feat; h = relu(BN(x) @ w_feat); stats(h) for conv0
    colstats_kernel<<<200, 128>>>(x, N_NODES);
    transform_kernel<<<1, 128>>>(w_feat, bnf_g, bnf_b, nullptr, 1.0f / N_NODES);
    gemm_kernel<<<gemm_blocks, 256>>>(x, 0, N_NODES, 1, nullptr, nullptr,
                                      GF_RELU | GF_STATS);

    for (int i = 0; i < 3; i++) {
        transform_kernel<<<1, 128>>>(gat_w + i * FDIM * FDIM,
                                     bnc_g + i * FDIM, bnc_b + i * FDIM,
                                     nullptr, 1.0f / N_NODES);
        gemm_kernel<<<gemm_blocks, 256>>>(nullptr, 1, N_NODES, 2,
                                          gat_asrc + i * HEADS * DHEAD,
                                          gat_adst + i * HEADS * DHEAD, GF_ALPHA);
        agg_kernel<<<agg_blocks, 256>>>(gat_b + i * FDIM, (i < 2) ? 1 : 0);
    }

    pool_kernel<<<pool_blocks, 256>>>(batch);
    colstats_g_kernel<<<8, 128>>>();
    transform_kernel<<<1, 128>>>(lin_w, bnfc_g, bnfc_b, lin_b, 1.0f / N_GRAPHS);
    gemm_kernel<<<(N_GRAPHS + 63) / 64, 256>>>(nullptr, 2, N_GRAPHS, 2,
                                               nullptr, nullptr, GF_RELU | GF_STATS);
    classifier_kernel<<<N_GRAPHS, 128>>>(bnh_g, bnh_b, cls_w, cls_b, out);
}

// round 7
// speedup vs baseline: 1.9527x; 1.0076x over previous
#include <cuda_runtime.h>
#include <math.h>

#define N_NODES  50000
#define N_EDGES  800000
#define FDIM     128
#define HEADS    4
#define DHEAD    32
#define N_GRAPHS 256
#define NCLS     10
#define BN_EPS   1e-5f
#define NEG_SLOPE 0.2f

#define GF_RELU  1
#define GF_ALPHA 2
#define GF_STATS 4

// ---------------- scratch (device globals; no allocation) ----------------
__device__ float d_h[N_NODES * FDIM];
__device__ float d_hw[N_NODES * FDIM];
__device__ float d_als[N_NODES * HEADS];
__device__ float d_ald[N_NODES * HEADS];
__device__ float d_stats[2 * FDIM];
__device__ float d_wp[FDIM * FDIM];
__device__ float d_bp[FDIM];
__device__ float d_g[N_GRAPHS * FDIM];
// CSR (built once per launch, reused for all 3 convs)
__device__ int   d_deg[N_NODES];
__device__ int   d_start[N_NODES + 1];
__device__ int   d_cursor[N_NODES];
__device__ int   d_ssrc[N_EDGES];
__device__ int   d_partial[256];

__device__ __forceinline__ float lrelu(float x) { return x > 0.f ? x : NEG_SLOPE * x; }

// ---------------- init ----------------
__global__ void zero_small_kernel() {
    int i = blockIdx.x * blockDim.x + threadIdx.x;
    if (i < 2 * FDIM) d_stats[i] = 0.f;
    if (i < N_GRAPHS * FDIM) d_g[i] = 0.f;
    if (i < N_NODES) d_deg[i] = 0;
}

// ---------------- CSR build ----------------
__global__ void csr_count_kernel(const int* __restrict__ edst) {
    int e = blockIdx.x * blockDim.x + threadIdx.x;
    if (e < N_EDGES) atomicAdd(&d_deg[edst[e]], 1);
}

#define SCAN_NB 256
#define SCAN_CHUNK ((N_NODES + SCAN_NB - 1) / SCAN_NB)   // 196

__global__ void scan1_kernel() {
    __shared__ int sred[256];
    int b = blockIdx.x, t = threadIdx.x;
    int idx = b * SCAN_CHUNK + t;
    int v = (t < SCAN_CHUNK && idx < N_NODES) ? d_deg[idx] : 0;
    sred[t] = v;
    __syncthreads();
    for (int off = 128; off > 0; off >>= 1) {
        if (t < off) sred[t] += sred[t + off];
        __syncthreads();
    }
    if (t == 0) d_partial[b] = sred[0];
}

__global__ void scan2_kernel() {
    if (threadIdx.x == 0) {
        int run = 0;
        for (int i = 0; i < SCAN_NB; i++) {
            int v = d_partial[i];
            d_partial[i] = run;
            run += v;
        }
    }
}

__global__ void scan3_kernel() {
    int b = blockIdx.x;
    if (threadIdx.x != 0) return;
    int run = d_partial[b];
    int i0 = b * SCAN_CHUNK;
    int i1 = min(i0 + SCAN_CHUNK, N_NODES);
    for (int i = i0; i < i1; i++) {
        d_start[i] = run;
        d_cursor[i] = run;
        run += d_deg[i];
    }
    if (i1 == N_NODES) d_start[N_NODES] = run;
}

__global__ void csr_scatter_kernel(const int* __restrict__ esrc,
                                   const int* __restrict__ edst) {
    int e = blockIdx.x * blockDim.x + threadIdx.x;
    if (e >= N_EDGES) return;
    int pos = atomicAdd(&d_cursor[edst[e]], 1);
    d_ssrc[pos] = esrc[e];
}

// ---------------- per-column stats ----------------
__global__ void colstats_kernel(const float* __restrict__ A, int rows) {
    int t = threadIdx.x;
    int per = (rows + gridDim.x - 1) / gridDim.x;
    int r0 = blockIdx.x * per;
    int r1 = min(r0 + per, rows);
    float s = 0.f, q = 0.f;
    for (int r = r0; r < r1; r++) {
        float v = A[(size_t)r * FDIM + t];
        s += v; q += v * v;
    }
    atomicAdd(&d_stats[t], s);
    atomicAdd(&d_stats[FDIM + t], q);
}

__global__ void colstats_g_kernel() {
    int t = threadIdx.x;
    int per = (N_GRAPHS + gridDim.x - 1) / gridDim.x;
    int r0 = blockIdx.x * per;
    int r1 = min(r0 + per, N_GRAPHS);
    float s = 0.f, q = 0.f;
    for (int r = r0; r < r1; r++) {
        float v = d_g[r * FDIM + t];
        s += v; q += v * v;
    }
    atomicAdd(&d_stats[t], s);
    atomicAdd(&d_stats[FDIM + t], q);
}

// ---------------- fold BN into weight ----------------
__global__ void transform_kernel(const float* __restrict__ W,
                                 const float* __restrict__ g,
                                 const float* __restrict__ b,
                                 const float* __restrict__ extra_bias,
                                 float inv_n) {
    int t = threadIdx.x;
    __shared__ float sc[FDIM], sh[FDIM];
    float mean = d_stats[t] * inv_n;
    float var  = d_stats[FDIM + t] * inv_n - mean * mean;
    float s = g[t] * rsqrtf(var + BN_EPS);
    sc[t] = s;
    sh[t] = b[t] - mean * s;
    d_stats[t] = 0.f;
    d_stats[FDIM + t] = 0.f;
    __syncthreads();
    float bp = extra_bias ? extra_bias[t] : 0.f;
    for (int k = 0; k < FDIM; k++) {
        float w = W[k * FDIM + t];
        d_wp[k * FDIM + t] = sc[k] * w;
        bp += sh[k] * w;
    }
    d_bp[t] = bp;
}

// ---------------- main GEMM with fused epilogues ----------------
__global__ void __launch_bounds__(256, 2)
gemm_kernel(const float* __restrict__ Aext, int asel, int M, int csel,
            const float* __restrict__ a_src, const float* __restrict__ a_dst,
            int flags) {
    __shared__ float Ws[32 * 128];
    __shared__ float sred[256];
    const float* A = (asel == 0) ? Aext
                    : (asel == 1 ? (const float*)d_h : (const float*)d_g);
    float* C = (csel == 1) ? (float*)d_h : (float*)d_hw;

    int tid = threadIdx.x;
    int tx = tid & 31, ty = tid >> 5;
    int row0 = blockIdx.x * 64 + ty * 8;

    const float4* pA[8];
#pragma unroll
    for (int r = 0; r < 8; r++) {
        int row = row0 + r; if (row >= M) row = M - 1;
        pA[r] = (const float4*)(A + (size_t)row * FDIM);
    }
    float acc[8][4];
#pragma unroll
    for (int r = 0; r < 8; r++) { acc[r][0] = acc[r][1] = acc[r][2] = acc[r][3] = 0.f; }

    for (int kt = 0; kt < 128; kt += 32) {
#pragma unroll
        for (int i = 0; i < 4; i++) {
            int idx = tid + i * 256;
            ((float4*)Ws)[idx] = ((const float4*)(d_wp + kt * 128))[idx];
        }
        __syncthreads();
#pragma unroll
        for (int k = 0; k < 32; k += 4) {
            float4 w0 = *(float4*)&Ws[(k + 0) * 128 + 4 * tx];
            float4 w1 = *(float4*)&Ws[(k + 1) * 128 + 4 * tx];
            float4 w2 = *(float4*)&Ws[(k + 2) * 128 + 4 * tx];
            float4 w3 = *(float4*)&Ws[(k + 3) * 128 + 4 * tx];
#pragma unroll
            for (int r = 0; r < 8; r++) {
                float4 a = __ldg(&pA[r][(kt + k) >> 2]);
                acc[r][0] += a.x * w0.x + a.y * w1.x + a.z * w2.x + a.w * w3.x;
                acc[r][1] += a.x * w0.y + a.y * w1.y + a.z * w2.y + a.w * w3.y;
                acc[r][2] += a.x * w0.z + a.y * w1.z + a.z * w2.z + a.w * w3.z;
                acc[r][3] += a.x * w0.w + a.y * w1.w + a.z * w2.w + a.w * w3.w;
            }
        }
        __syncthreads();
    }

    float4 bp4 = *(const float4*)&d_bp[4 * tx];
    int head = tx >> 3;
    float4 av_s = make_float4(0, 0, 0, 0), av_d = make_float4(0, 0, 0, 0);
    if (flags & GF_ALPHA) {
        av_s = *(const float4*)&a_src[head * DHEAD + 4 * (tx & 7)];
        av_d = *(const float4*)&a_dst[head * DHEAD + 4 * (tx & 7)];
    }
    float ss0 = 0, ss1 = 0, ss2 = 0, ss3 = 0;
    float sq0 = 0, sq1 = 0, sq2 = 0, sq3 = 0;
#pragma unroll
    for (int r = 0; r < 8; r++) {
        int row = row0 + r;
        if (row >= M) break;                        // uniform per warp
        float4 v;
        v.x = acc[r][0] + bp4.x; v.y = acc[r][1] + bp4.y;
        v.z = acc[r][2] + bp4.z; v.w = acc[r][3] + bp4.w;
        if (flags & GF_ALPHA) {
            float ps = v.x * av_s.x + v.y * av_s.y + v.z * av_s.z + v.w * av_s.w;
            float pd = v.x * av_d.x + v.y * av_d.y + v.z * av_d.z + v.w * av_d.w;
#pragma unroll
            for (int off = 4; off > 0; off >>= 1) {
                ps += __shfl_down_sync(0xffffffffu, ps, off, 8);
                pd += __shfl_down_sync(0xffffffffu, pd, off, 8);
            }
            if ((tx & 7) == 0) {
                d_als[row * HEADS + head] = ps;
                d_ald[row * HEADS + head] = pd;
            }
        }
        if (flags & GF_RELU) {
            v.x = fmaxf(v.x, 0.f); v.y = fmaxf(v.y, 0.f);
            v.z = fmaxf(v.z, 0.f); v.w = fmaxf(v.w, 0.f);
        }
        *(float4*)&C[(size_t)row * FDIM + 4 * tx] = v;
        ss0 += v.x; ss1 += v.y; ss2 += v.z; ss3 += v.w;
        sq0 += v.x * v.x; sq1 += v.y * v.y; sq2 += v.z * v.z; sq3 += v.w * v.w;
    }
    if (flags & GF_STATS) {
        sred[tid] = 0.f;
        __syncthreads();
        atomicAdd(&sred[4 * tx + 0], ss0); atomicAdd(&sred[4 * tx + 1], ss1);
        atomicAdd(&sred[4 * tx + 2], ss2); atomicAdd(&sred[4 * tx + 3], ss3);
        atomicAdd(&sred[128 + 4 * tx + 0], sq0); atomicAdd(&sred[128 + 4 * tx + 1], sq1);
        atomicAdd(&sred[128 + 4 * tx + 2], sq2); atomicAdd(&sred[128 + 4 * tx + 3], sq3);
        __syncthreads();
        atomicAdd(&d_stats[tid], sred[tid]);
    }
}

// ---------------- fused GAT aggregation (warp per dst node) ----------------
// softmax shift-invariance: out = (sum_e exp(l_e) * hw[src_e]) / (sum_e exp(l_e) + eps)
// (the segment-max shift cancels exactly; logits are O(1) so no overflow)
__global__ void __launch_bounds__(256)
agg_kernel(const float* __restrict__ bias, int do_stats) {
    __shared__ float sred[256];
    int tid = threadIdx.x;
    int lane = tid & 31;
    int n = blockIdx.x * 8 + (tid >> 5);
    int head = lane >> 3;

    float ss0 = 0, ss1 = 0, ss2 = 0, ss3 = 0;
    float sq0 = 0, sq1 = 0, sq2 = 0, sq3 = 0;

    if (n < N_NODES) {
        float aldv = d_ald[n * HEADS + head];
        // self-loop contribution
        float e = __expf(lrelu(d_als[n * HEADS + head] + aldv));
        float4 hv = *(const float4*)&d_hw[(size_t)n * FDIM + lane * 4];
        float4 acc = make_float4(e * hv.x, e * hv.y, e * hv.z, e * hv.w);
        float S = e;

        int p = d_start[n];
        int pend = d_start[n + 1];
        // one-ahead prefetch of src index + attention term
        int s_nx = 0; float a_nx = 0.f;
        if (p < pend) {
            s_nx = __ldg(&d_ssrc[p]);
            a_nx = __ldg(&d_als[s_nx * HEADS + head]);
        }
        for (; p < pend; p++) {
            int s = s_nx;
            float av = a_nx;
            if (p + 1 < pend) {
                s_nx = __ldg(&d_ssrc[p + 1]);
                a_nx = __ldg(&d_als[s_nx * HEADS + head]);
            }
            float4 h4 = __ldg((const float4*)&d_hw[(size_t)s * FDIM + lane * 4]);
            float ee = __expf(lrelu(av + aldv));
            S += ee;
            acc.x += ee * h4.x; acc.y += ee * h4.y;
            acc.z += ee * h4.z; acc.w += ee * h4.w;
        }
        float inv = 1.0f / (S + 1e-16f);
        float4 bv = *(const float4*)&bias[lane * 4];
        float4 v;
        v.x = fmaxf(acc.x * inv + bv.x, 0.f);
        v.y = fmaxf(acc.y * inv + bv.y, 0.f);
        v.z = fmaxf(acc.z * inv + bv.z, 0.f);
        v.w = fmaxf(acc.w * inv + bv.w, 0.f);
        *(float4*)&d_h[(size_t)n * FDIM + lane * 4] = v;
        ss0 = v.x; ss1 = v.y; ss2 = v.z; ss3 = v.w;
        sq0 = v.x * v.x; sq1 = v.y * v.y; sq2 = v.z * v.z; sq3 = v.w * v.w;
    }

    if (do_stats) {
        sred[tid] = 0.f;
        __syncthreads();
        atomicAdd(&sred[4 * lane + 0], ss0); atomicAdd(&sred[4 * lane + 1], ss1);
        atomicAdd(&sred[4 * lane + 2], ss2); atomicAdd(&sred[4 * lane + 3], ss3);
        atomicAdd(&sred[128 + 4 * lane + 0], sq0); atomicAdd(&sred[128 + 4 * lane + 1], sq1);
        atomicAdd(&sred[128 + 4 * lane + 2], sq2); atomicAdd(&sred[128 + 4 * lane + 3], sq3);
        __syncthreads();
        atomicAdd(&d_stats[tid], sred[tid]);
    }
}

// ---------------- global add pool ----------------
__global__ void pool_kernel(const int* __restrict__ batch) {
    int gt = blockIdx.x * blockDim.x + threadIdx.x;
    int n = gt >> 5;
    if (n >= N_NODES) return;
    int lane = gt & 31;
    int gi = batch[n];
    float4 v = *(const float4*)&d_h[(size_t)n * FDIM + lane * 4];
    atomicAdd((float4*)&d_g[gi * FDIM + lane * 4], v);
}

// ---------------- BN(g2) + classifier + log_softmax ----------------
__global__ void classifier_kernel(const float* __restrict__ bnh_g,
                                  const float* __restrict__ bnh_b,
                                  const float* __restrict__ cls_w,
                                  const float* __restrict__ cls_b,
                                  float* __restrict__ out) {
    int gi = blockIdx.x, t = threadIdx.x;
    float mean = d_stats[t] * (1.0f / N_GRAPHS);
    float var  = d_stats[FDIM + t] * (1.0f / N_GRAPHS) - mean * mean;
    float v = (d_hw[gi * FDIM + t] - mean) * rsqrtf(var + BN_EPS) * bnh_g[t] + bnh_b[t];
    __shared__ float sh[128];
    __shared__ float z[16];
    for (int c = 0; c < NCLS; c++) {
        sh[t] = v * cls_w[t * NCLS + c];
        __syncthreads();
        if (t < 64) sh[t] += sh[t + 64];
        __syncthreads();
        if (t < 32) {
            float s = sh[t] + sh[t + 32];
#pragma unroll
            for (int off = 16; off > 0; off >>= 1)
                s += __shfl_down_sync(0xffffffffu, s, off);
            if (t == 0) z[c] = s + cls_b[c];
        }
        __syncthreads();
    }
    if (t == 0) {
        float m = z[0];
        for (int c = 1; c < NCLS; c++) m = fmaxf(m, z[c]);
        float se = 0.f;
        for (int c = 0; c < NCLS; c++) se += expf(z[c] - m);
        float lse = m + logf(se);
        for (int c = 0; c < NCLS; c++) out[gi * NCLS + c] = z[c] - lse;
    }
}

// ---------------- launch ----------------
extern "C" void kernel_launch(void* const* d_in, const int* in_sizes, int n_in,
                              void* d_out, int out_size) {
    const float* x        = (const float*)d_in[0];
    const int*   eidx     = (const int*)d_in[1];
    const int*   batch    = (const int*)d_in[2];
    const float* w_feat   = (const float*)d_in[3];
    const float* bnf_g    = (const float*)d_in[4];
    const float* bnf_b    = (const float*)d_in[5];
    const float* bnc_g    = (const float*)d_in[6];
    const float* bnc_b    = (const float*)d_in[7];
    const float* gat_w    = (const float*)d_in[8];
    const float* gat_asrc = (const float*)d_in[9];
    const float* gat_adst = (const float*)d_in[10];
    const float* gat_b    = (const float*)d_in[11];
    const float* bnfc_g   = (const float*)d_in[12];
    const float* bnfc_b   = (const float*)d_in[13];
    const float* lin_w    = (const float*)d_in[14];
    const float* lin_b    = (const float*)d_in[15];
    const float* bnh_g    = (const float*)d_in[16];
    const float* bnh_b    = (const float*)d_in[17];
    const float* cls_w    = (const float*)d_in[18];
    const float* cls_b    = (const float*)d_in[19];
    float* out = (float*)d_out;

    const int* esrc = eidx;
    const int* edst = eidx + N_EDGES;

    const int gemm_blocks = (N_NODES + 63) / 64;
    const int edge_blocks = (N_EDGES + 255) / 256;
    const int agg_blocks  = (N_NODES + 7) / 8;
    const int pool_blocks = (N_NODES * 32 + 255) / 256;

    // init + CSR build (reused for all 3 convs)
    zero_small_kernel<<<(N_NODES + 255) / 256, 256>>>();
    csr_count_kernel<<<edge_blocks, 256>>>(edst);
    scan1_kernel<<<SCAN_NB, 256>>>();
    scan2_kernel<<<1, 32>>>();
    scan3_kernel<<<SCAN_NB, 32>>>();
    csr_scatter_kernel<<<edge_blocks, 256>>>(esrc, edst);

    // bn_feat folded into w_feat; h = relu(BN(x) @ w_feat); stats(h) for conv0
    colstats_kernel<<<200, 128>>>(x, N_NODES);
    transform_kernel<<<1, 128>>>(w_feat, bnf_g, bnf_b, nullptr, 1.0f / N_NODES);
    gemm_kernel<<<gemm_blocks, 256>>>(x, 0, N_NODES, 1, nullptr, nullptr,
                                      GF_RELU | GF_STATS);

    for (int i = 0; i < 3; i++) {
        transform_kernel<<<1, 128>>>(gat_w + i * FDIM * FDIM,
                                     bnc_g + i * FDIM, bnc_b + i * FDIM,
                                     nullptr, 1.0f / N_NODES);
        gemm_kernel<<<gemm_blocks, 256>>>(nullptr, 1, N_NODES, 2,
                                          gat_asrc + i * HEADS * DHEAD,
                                          gat_adst + i * HEADS * DHEAD, GF_ALPHA);
        agg_kernel<<<agg_blocks, 256>>>(gat_b + i * FDIM, (i < 2) ? 1 : 0);
    }

    pool_kernel<<<pool_blocks, 256>>>(batch);
    colstats_g_kernel<<<8, 128>>>();
    transform_kernel<<<1, 128>>>(lin_w, bnfc_g, bnfc_b, lin_b, 1.0f / N_GRAPHS);
    gemm_kernel<<<(N_GRAPHS + 63) / 64, 256>>>(nullptr, 2, N_GRAPHS, 2,
                                               nullptr, nullptr, GF_RELU | GF_STATS);
    classifier_kernel<<<N_GRAPHS, 128>>>(bnh_g, bnh_b, cls_w, cls_b, out);
}

// round 8
// speedup vs baseline: 2.1168x; 1.0840x over previous
#include <cuda_runtime.h>
#include <math.h>

#define N_NODES  50000
#define N_EDGES  800000
#define FDIM     128
#define HEADS    4
#define DHEAD    32
#define N_GRAPHS 256
#define NCLS     10
#define BN_EPS   1e-5f
#define NEG_SLOPE 0.2f

#define GF_RELU  1
#define GF_ALPHA 2
#define GF_STATS 4

// ---------------- scratch (device globals; no allocation) ----------------
__device__ float d_h[N_NODES * FDIM];
__device__ float d_hw[N_NODES * FDIM];
__device__ float d_als[N_NODES * HEADS];
__device__ float d_ald[N_NODES * HEADS];
__device__ float d_stats[2 * FDIM];
__device__ float d_wp[FDIM * FDIM];
__device__ float d_bp[FDIM];
__device__ float d_g[N_GRAPHS * FDIM];
// CSR (built once per launch, reused for all 3 convs)
__device__ int   d_deg[N_NODES];
__device__ int   d_start[N_NODES + 1];
__device__ int   d_cursor[N_NODES];
__device__ int   d_ssrc[N_EDGES];
__device__ int   d_partial[256];

__device__ __forceinline__ float lrelu(float x) { return x > 0.f ? x : NEG_SLOPE * x; }

// ---------------- init ----------------
__global__ void zero_small_kernel() {
    int i = blockIdx.x * blockDim.x + threadIdx.x;
    if (i < 2 * FDIM) d_stats[i] = 0.f;
    if (i < N_GRAPHS * FDIM) d_g[i] = 0.f;
    if (i < N_NODES) d_deg[i] = 0;
}

// ---------------- CSR build ----------------
__global__ void csr_count_kernel(const int* __restrict__ edst) {
    int e = blockIdx.x * blockDim.x + threadIdx.x;
    if (e < N_EDGES) atomicAdd(&d_deg[edst[e]], 1);
}

#define SCAN_NB 256
#define SCAN_CHUNK ((N_NODES + SCAN_NB - 1) / SCAN_NB)   // 196

__global__ void scan1_kernel() {
    __shared__ int sred[256];
    int b = blockIdx.x, t = threadIdx.x;
    int idx = b * SCAN_CHUNK + t;
    int v = (t < SCAN_CHUNK && idx < N_NODES) ? d_deg[idx] : 0;
    sred[t] = v;
    __syncthreads();
    for (int off = 128; off > 0; off >>= 1) {
        if (t < off) sred[t] += sred[t + off];
        __syncthreads();
    }
    if (t == 0) d_partial[b] = sred[0];
}

// parallel exclusive scan over the 256 block partials
__global__ void scan2_kernel() {
    __shared__ int sm[256];
    int t = threadIdx.x;
    int v = d_partial[t];
    sm[t] = v;
    __syncthreads();
    for (int off = 1; off < 256; off <<= 1) {
        int x = (t >= off) ? sm[t - off] : 0;
        __syncthreads();
        sm[t] += x;
        __syncthreads();
    }
    d_partial[t] = sm[t] - v;   // exclusive
}

__global__ void scan3_kernel() {
    int b = blockIdx.x;
    if (threadIdx.x != 0) return;
    int run = d_partial[b];
    int i0 = b * SCAN_CHUNK;
    int i1 = min(i0 + SCAN_CHUNK, N_NODES);
    for (int i = i0; i < i1; i++) {
        d_start[i] = run;
        d_cursor[i] = run;
        run += d_deg[i];
    }
    if (i1 == N_NODES) d_start[N_NODES] = run;
}

__global__ void csr_scatter_kernel(const int* __restrict__ esrc,
                                   const int* __restrict__ edst) {
    int e = blockIdx.x * blockDim.x + threadIdx.x;
    if (e >= N_EDGES) return;
    int pos = atomicAdd(&d_cursor[edst[e]], 1);
    d_ssrc[pos] = esrc[e];
}

// ---------------- per-column stats ----------------
__global__ void colstats_kernel(const float* __restrict__ A, int rows) {
    int t = threadIdx.x;
    int per = (rows + gridDim.x - 1) / gridDim.x;
    int r0 = blockIdx.x * per;
    int r1 = min(r0 + per, rows);
    float s = 0.f, q = 0.f;
    for (int r = r0; r < r1; r++) {
        float v = A[(size_t)r * FDIM + t];
        s += v; q += v * v;
    }
    atomicAdd(&d_stats[t], s);
    atomicAdd(&d_stats[FDIM + t], q);
}

__global__ void colstats_g_kernel() {
    int t = threadIdx.x;
    int per = (N_GRAPHS + gridDim.x - 1) / gridDim.x;
    int r0 = blockIdx.x * per;
    int r1 = min(r0 + per, N_GRAPHS);
    float s = 0.f, q = 0.f;
    for (int r = r0; r < r1; r++) {
        float v = d_g[r * FDIM + t];
        s += v; q += v * v;
    }
    atomicAdd(&d_stats[t], s);
    atomicAdd(&d_stats[FDIM + t], q);
}

// ---------------- fold BN into weight ----------------
__global__ void transform_kernel(const float* __restrict__ W,
                                 const float* __restrict__ g,
                                 const float* __restrict__ b,
                                 const float* __restrict__ extra_bias,
                                 float inv_n) {
    int t = threadIdx.x;
    __shared__ float sc[FDIM], sh[FDIM];
    float mean = d_stats[t] * inv_n;
    float var  = d_stats[FDIM + t] * inv_n - mean * mean;
    float s = g[t] * rsqrtf(var + BN_EPS);
    sc[t] = s;
    sh[t] = b[t] - mean * s;
    d_stats[t] = 0.f;
    d_stats[FDIM + t] = 0.f;
    __syncthreads();
    float bp = extra_bias ? extra_bias[t] : 0.f;
    for (int k = 0; k < FDIM; k++) {
        float w = W[k * FDIM + t];
        d_wp[k * FDIM + t] = sc[k] * w;
        bp += sh[k] * w;
    }
    d_bp[t] = bp;
}

// ---------------- 128x128-tile SGEMM, 8x8 per thread, fused epilogues ------
// C[M,128] = A[M,128] @ d_wp + d_bp ; optional relu / alpha / stats
__global__ void __launch_bounds__(256, 2)
gemm_kernel(const float* __restrict__ Aext, int asel, int M, int csel,
            const float* __restrict__ a_src, const float* __restrict__ a_dst,
            int flags) {
    __shared__ float As[16 * 132];     // [k][m], padded row stride 132
    __shared__ float Bs[16 * 128];     // [k][n]
    __shared__ float sstat[256];
    const float* A = (asel == 0) ? Aext
                    : (asel == 1 ? (const float*)d_h : (const float*)d_g);
    float* C = (csel == 1) ? (float*)d_h : (float*)d_hw;

    int tid = threadIdx.x;
    int tn = tid & 15, tm = tid >> 4;
    int row_base = blockIdx.x * 128;

    // A slab loaders: f = tid + 256*i -> row = f>>2, kq = f&3
    int ar0 = tid >> 2, akq = tid & 3;
    int ar1 = (tid + 256) >> 2;
    size_t grow0 = (size_t)min(row_base + ar0, M - 1);
    size_t grow1 = (size_t)min(row_base + ar1, M - 1);
    const float4* A4 = (const float4*)A;
    const float4* W4 = (const float4*)d_wp;

    float acc[8][8];
#pragma unroll
    for (int i = 0; i < 8; i++)
#pragma unroll
        for (int j = 0; j < 8; j++) acc[i][j] = 0.f;

    // prefetch slab 0
    float4 pa0 = __ldg(&A4[grow0 * 32 + akq]);
    float4 pa1 = __ldg(&A4[grow1 * 32 + akq]);
    float4 pb0 = W4[tid];
    float4 pb1 = W4[tid + 256];

    for (int s = 0; s < 8; s++) {
        // commit prefetched slab to smem (A transposed [k][m])
        As[(akq * 4 + 0) * 132 + ar0] = pa0.x;
        As[(akq * 4 + 1) * 132 + ar0] = pa0.y;
        As[(akq * 4 + 2) * 132 + ar0] = pa0.z;
        As[(akq * 4 + 3) * 132 + ar0] = pa0.w;
        As[(akq * 4 + 0) * 132 + ar1] = pa1.x;
        As[(akq * 4 + 1) * 132 + ar1] = pa1.y;
        As[(akq * 4 + 2) * 132 + ar1] = pa1.z;
        As[(akq * 4 + 3) * 132 + ar1] = pa1.w;
        ((float4*)Bs)[tid] = pb0;
        ((float4*)Bs)[tid + 256] = pb1;
        __syncthreads();
        if (s < 7) {
            pa0 = __ldg(&A4[grow0 * 32 + (s + 1) * 4 + akq]);
            pa1 = __ldg(&A4[grow1 * 32 + (s + 1) * 4 + akq]);
            pb0 = W4[(s + 1) * 512 + tid];
            pb1 = W4[(s + 1) * 512 + tid + 256];
        }
#pragma unroll
        for (int k = 0; k < 16; k++) {
            float4 a0 = *(float4*)&As[k * 132 + tm * 4];
            float4 a1 = *(float4*)&As[k * 132 + tm * 4 + 64];
            float4 b0 = *(float4*)&Bs[k * 128 + tn * 4];
            float4 b1 = *(float4*)&Bs[k * 128 + tn * 4 + 64];
            float av[8] = {a0.x, a0.y, a0.z, a0.w, a1.x, a1.y, a1.z, a1.w};
            float bv[8] = {b0.x, b0.y, b0.z, b0.w, b1.x, b1.y, b1.z, b1.w};
#pragma unroll
            for (int i = 0; i < 8; i++)
#pragma unroll
                for (int j = 0; j < 8; j++)
                    acc[i][j] += av[i] * bv[j];
        }
        __syncthreads();
    }

    // ---- epilogue ----
    float bpv[8];
    *(float4*)&bpv[0] = *(const float4*)&d_bp[tn * 4];
    *(float4*)&bpv[4] = *(const float4*)&d_bp[tn * 4 + 64];
    float asl[8], adl[8];
    if (flags & GF_ALPHA) {
        *(float4*)&asl[0] = *(const float4*)&a_src[tn * 4];
        *(float4*)&asl[4] = *(const float4*)&a_src[tn * 4 + 64];
        *(float4*)&adl[0] = *(const float4*)&a_dst[tn * 4];
        *(float4*)&adl[4] = *(const float4*)&a_dst[tn * 4 + 64];
    }
    if (flags & GF_STATS) sstat[tid] = 0.f;

    float ss[8], sq[8];
#pragma unroll
    for (int j = 0; j < 8; j++) { ss[j] = 0.f; sq[j] = 0.f; }

#pragma unroll
    for (int i = 0; i < 8; i++) {
        int m_local = (i < 4) ? (tm * 4 + i) : (tm * 4 + 64 + i - 4);
        int row = row_base + m_local;
        bool ok = (row < M);
        float v[8];
#pragma unroll
        for (int j = 0; j < 8; j++) v[j] = acc[i][j] + bpv[j];
        if (flags & GF_ALPHA) {
            // lanes: (tm&1)*16 + tn ; tn 0-7 -> head lo, tn 8-15 -> head lo+1
            float pl = v[0]*asl[0] + v[1]*asl[1] + v[2]*asl[2] + v[3]*asl[3];
            float ph = v[4]*asl[4] + v[5]*asl[5] + v[6]*asl[6] + v[7]*asl[7];
            float ql = v[0]*adl[0] + v[1]*adl[1] + v[2]*adl[2] + v[3]*adl[3];
            float qh = v[4]*adl[4] + v[5]*adl[5] + v[6]*adl[6] + v[7]*adl[7];
#pragma unroll
            for (int off = 4; off > 0; off >>= 1) {
                pl += __shfl_down_sync(0xffffffffu, pl, off, 8);
                ph += __shfl_down_sync(0xffffffffu, ph, off, 8);
                ql += __shfl_down_sync(0xffffffffu, ql, off, 8);
                qh += __shfl_down_sync(0xffffffffu, qh, off, 8);
            }
            if (ok && (tn & 7) == 0) {
                int hbase = tn >> 3;            // 0 or 1
                d_als[row * HEADS + hbase]     = pl;
                d_als[row * HEADS + hbase + 2] = ph;
                d_ald[row * HEADS + hbase]     = ql;
                d_ald[row * HEADS + hbase + 2] = qh;
            }
        }
        if (flags & GF_RELU) {
#pragma unroll
            for (int j = 0; j < 8; j++) v[j] = fmaxf(v[j], 0.f);
        }
        if (ok) {
            *(float4*)&C[(size_t)row * FDIM + tn * 4]      = *(float4*)&v[0];
            *(float4*)&C[(size_t)row * FDIM + tn * 4 + 64] = *(float4*)&v[4];
#pragma unroll
            for (int j = 0; j < 8; j++) { ss[j] += v[j]; sq[j] += v[j] * v[j]; }
        }
    }

    if (flags & GF_STATS) {
        __syncthreads();
#pragma unroll
        for (int j = 0; j < 8; j++) {
            int col = (j < 4) ? (tn * 4 + j) : (tn * 4 + 64 + j - 4);
            atomicAdd(&sstat[col], ss[j]);
            atomicAdd(&sstat[128 + col], sq[j]);
        }
        __syncthreads();
        atomicAdd(&d_stats[tid], sstat[tid]);
    }
}

// ---------------- fused GAT aggregation (warp per dst node) ----------------
// out = (sum_e exp(l_e) * hw[src_e]) / (sum_e exp(l_e) + eps) — max shift cancels
__global__ void __launch_bounds__(256)
agg_kernel(const float* __restrict__ bias, int do_stats) {
    __shared__ float sred[256];
    int tid = threadIdx.x;
    int lane = tid & 31;
    int n = blockIdx.x * 8 + (tid >> 5);
    int head = lane >> 3;

    float ss0 = 0, ss1 = 0, ss2 = 0, ss3 = 0;
    float sq0 = 0, sq1 = 0, sq2 = 0, sq3 = 0;

    if (n < N_NODES) {
        float aldv = d_ald[n * HEADS + head];
        // self-loop contribution
        float e = __expf(lrelu(d_als[n * HEADS + head] + aldv));
        float4 hv = *(const float4*)&d_hw[(size_t)n * FDIM + lane * 4];
        float4 acc = make_float4(e * hv.x, e * hv.y, e * hv.z, e * hv.w);
        float S = e;

        int p = d_start[n];
        int pend = d_start[n + 1];
        // 4-deep pipelined main loop (MLP boost)
        for (; p + 3 < pend; p += 4) {
            int s0 = __ldg(&d_ssrc[p + 0]);
            int s1 = __ldg(&d_ssrc[p + 1]);
            int s2 = __ldg(&d_ssrc[p + 2]);
            int s3 = __ldg(&d_ssrc[p + 3]);
            float4 h0 = __ldg((const float4*)&d_hw[(size_t)s0 * FDIM + lane * 4]);
            float4 h1 = __ldg((const float4*)&d_hw[(size_t)s1 * FDIM + lane * 4]);
            float4 h2 = __ldg((const float4*)&d_hw[(size_t)s2 * FDIM + lane * 4]);
            float4 h3 = __ldg((const float4*)&d_hw[(size_t)s3 * FDIM + lane * 4]);
            float a0 = __ldg(&d_als[s0 * HEADS + head]);
            float a1 = __ldg(&d_als[s1 * HEADS + head]);
            float a2 = __ldg(&d_als[s2 * HEADS + head]);
            float a3 = __ldg(&d_als[s3 * HEADS + head]);
            float e0 = __expf(lrelu(a0 + aldv));
            float e1 = __expf(lrelu(a1 + aldv));
            float e2 = __expf(lrelu(a2 + aldv));
            float e3 = __expf(lrelu(a3 + aldv));
            S += (e0 + e1) + (e2 + e3);
            acc.x += e0 * h0.x + e1 * h1.x + e2 * h2.x + e3 * h3.x;
            acc.y += e0 * h0.y + e1 * h1.y + e2 * h2.y + e3 * h3.y;
            acc.z += e0 * h0.z + e1 * h1.z + e2 * h2.z + e3 * h3.z;
            acc.w += e0 * h0.w + e1 * h1.w + e2 * h2.w + e3 * h3.w;
        }
        for (; p < pend; p++) {
            int s = __ldg(&d_ssrc[p]);
            float av = __ldg(&d_als[s * HEADS + head]);
            float4 h4 = __ldg((const float4*)&d_hw[(size_t)s * FDIM + lane * 4]);
            float ee = __expf(lrelu(av + aldv));
            S += ee;
            acc.x += ee * h4.x; acc.y += ee * h4.y;
            acc.z += ee * h4.z; acc.w += ee * h4.w;
        }
        float inv = 1.0f / (S + 1e-16f);
        float4 bv = *(const float4*)&bias[lane * 4];
        float4 v;
        v.x = fmaxf(acc.x * inv + bv.x, 0.f);
        v.y = fmaxf(acc.y * inv + bv.y, 0.f);
        v.z = fmaxf(acc.z * inv + bv.z, 0.f);
        v.w = fmaxf(acc.w * inv + bv.w, 0.f);
        *(float4*)&d_h[(size_t)n * FDIM + lane * 4] = v;
        ss0 = v.x; ss1 = v.y; ss2 = v.z; ss3 = v.w;
        sq0 = v.x * v.x; sq1 = v.y * v.y; sq2 = v.z * v.z; sq3 = v.w * v.w;
    }

    if (do_stats) {
        sred[tid] = 0.f;
        __syncthreads();
        atomicAdd(&sred[4 * lane + 0], ss0); atomicAdd(&sred[4 * lane + 1], ss1);
        atomicAdd(&sred[4 * lane + 2], ss2); atomicAdd(&sred[4 * lane + 3], ss3);
        atomicAdd(&sred[128 + 4 * lane + 0], sq0); atomicAdd(&sred[128 + 4 * lane + 1], sq1);
        atomicAdd(&sred[128 + 4 * lane + 2], sq2); atomicAdd(&sred[128 + 4 * lane + 3], sq3);
        __syncthreads();
        atomicAdd(&d_stats[tid], sred[tid]);
    }
}

// ---------------- global add pool ----------------
__global__ void pool_kernel(const int* __restrict__ batch) {
    int gt = blockIdx.x * blockDim.x + threadIdx.x;
    int n = gt >> 5;
    if (n >= N_NODES) return;
    int lane = gt & 31;
    int gi = batch[n];
    float4 v = *(const float4*)&d_h[(size_t)n * FDIM + lane * 4];
    atomicAdd((float4*)&d_g[gi * FDIM + lane * 4], v);
}

// ---------------- BN(g2) + classifier + log_softmax ----------------
__global__ void classifier_kernel(const float* __restrict__ bnh_g,
                                  const float* __restrict__ bnh_b,
                                  const float* __restrict__ cls_w,
                                  const float* __restrict__ cls_b,
                                  float* __restrict__ out) {
    int gi = blockIdx.x, t = threadIdx.x;
    float mean = d_stats[t] * (1.0f / N_GRAPHS);
    float var  = d_stats[FDIM + t] * (1.0f / N_GRAPHS) - mean * mean;
    float v = (d_hw[gi * FDIM + t] - mean) * rsqrtf(var + BN_EPS) * bnh_g[t] + bnh_b[t];
    __shared__ float sh[128];
    __shared__ float z[16];
    for (int c = 0; c < NCLS; c++) {
        sh[t] = v * cls_w[t * NCLS + c];
        __syncthreads();
        if (t < 64) sh[t] += sh[t + 64];
        __syncthreads();
        if (t < 32) {
            float s = sh[t] + sh[t + 32];
#pragma unroll
            for (int off = 16; off > 0; off >>= 1)
                s += __shfl_down_sync(0xffffffffu, s, off);
            if (t == 0) z[c] = s + cls_b[c];
        }
        __syncthreads();
    }
    if (t == 0) {
        float m = z[0];
        for (int c = 1; c < NCLS; c++) m = fmaxf(m, z[c]);
        float se = 0.f;
        for (int c = 0; c < NCLS; c++) se += expf(z[c] - m);
        float lse = m + logf(se);
        for (int c = 0; c < NCLS; c++) out[gi * NCLS + c] = z[c] - lse;
    }
}

// ---------------- launch ----------------
extern "C" void kernel_launch(void* const* d_in, const int* in_sizes, int n_in,
                              void* d_out, int out_size) {
    const float* x        = (const float*)d_in[0];
    const int*   eidx     = (const int*)d_in[1];
    const int*   batch    = (const int*)d_in[2];
    const float* w_feat   = (const float*)d_in[3];
    const float* bnf_g    = (const float*)d_in[4];
    const float* bnf_b    = (const float*)d_in[5];
    const float* bnc_g    = (const float*)d_in[6];
    const float* bnc_b    = (const float*)d_in[7];
    const float* gat_w    = (const float*)d_in[8];
    const float* gat_asrc = (const float*)d_in[9];
    const float* gat_adst = (const float*)d_in[10];
    const float* gat_b    = (const float*)d_in[11];
    const float* bnfc_g   = (const float*)d_in[12];
    const float* bnfc_b   = (const float*)d_in[13];
    const float* lin_w    = (const float*)d_in[14];
    const float* lin_b    = (const float*)d_in[15];
    const float* bnh_g    = (const float*)d_in[16];
    const float* bnh_b    = (const float*)d_in[17];
    const float* cls_w    = (const float*)d_in[18];
    const float* cls_b    = (const float*)d_in[19];
    float* out = (float*)d_out;

    const int* esrc = eidx;
    const int* edst = eidx + N_EDGES;

    const int gemm_blocks = (N_NODES + 127) / 128;
    const int edge_blocks = (N_EDGES + 255) / 256;
    const int agg_blocks  = (N_NODES + 7) / 8;
    const int pool_blocks = (N_NODES * 32 + 255) / 256;

    // init + CSR build (reused for all 3 convs)
    zero_small_kernel<<<(N_NODES + 255) / 256, 256>>>();
    csr_count_kernel<<<edge_blocks, 256>>>(edst);
    scan1_kernel<<<SCAN_NB, 256>>>();
    scan2_kernel<<<1, 256>>>();
    scan3_kernel<<<SCAN_NB, 32>>>();
    csr_scatter_kernel<<<edge_blocks, 256>>>(esrc, edst);

    // bn_feat folded into w_feat; h = relu(BN(x) @ w_feat); stats(h) for conv0
    colstats_kernel<<<200, 128>>>(x, N_NODES);
    transform_kernel<<<1, 128>>>(w_feat, bnf_g, bnf_b, nullptr, 1.0f / N_NODES);
    gemm_kernel<<<gemm_blocks, 256>>>(x, 0, N_NODES, 1, nullptr, nullptr,
                                      GF_RELU | GF_STATS);

    for (int i = 0; i < 3; i++) {
        transform_kernel<<<1, 128>>>(gat_w + i * FDIM * FDIM,
                                     bnc_g + i * FDIM, bnc_b + i * FDIM,
                                     nullptr, 1.0f / N_NODES);
        gemm_kernel<<<gemm_blocks, 256>>>(nullptr, 1, N_NODES, 2,
                                          gat_asrc + i * HEADS * DHEAD,
                                          gat_adst + i * HEADS * DHEAD, GF_ALPHA);
        agg_kernel<<<agg_blocks, 256>>>(gat_b + i * FDIM, (i < 2) ? 1 : 0);
    }

    pool_kernel<<<pool_blocks, 256>>>(batch);
    colstats_g_kernel<<<8, 128>>>();
    transform_kernel<<<1, 128>>>(lin_w, bnfc_g, bnfc_b, lin_b, 1.0f / N_GRAPHS);
    gemm_kernel<<<(N_GRAPHS + 127) / 128, 256>>>(nullptr, 2, N_GRAPHS, 2,
                                                 nullptr, nullptr, GF_RELU | GF_STATS);
    classifier_kernel<<<N_GRAPHS, 128>>>(bnh_g, bnh_b, cls_w, cls_b, out);
}

// round 9
// speedup vs baseline: 2.5054x; 1.1836x over previous
#include <cuda_runtime.h>
#include <math.h>

#define N_NODES  50000
#define N_EDGES  800000
#define FDIM     128
#define HEADS    4
#define DHEAD    32
#define N_GRAPHS 256
#define NCLS     10
#define BN_EPS   1e-5f
#define NEG_SLOPE 0.2f

#define GF_RELU  1
#define GF_ALPHA 2
#define GF_STATS 4

// ---------------- scratch (device globals; no allocation) ----------------
__device__ float d_h[N_NODES * FDIM];
__device__ float d_hw[N_NODES * FDIM];
__device__ float d_als[N_NODES * HEADS];
__device__ float d_ald[N_NODES * HEADS];
__device__ float d_stats[6 * 256];          // 6 slots: [sums(128) | sumsq(128)]
__device__ float d_wp[FDIM * FDIM];
__device__ float d_bp[5 * FDIM];            // 5 bias slots (one per transform)
__device__ float d_g[N_GRAPHS * FDIM];
// CSR (built once per launch, reused for all 3 convs)
__device__ int   d_deg[N_NODES];
__device__ int   d_start[N_NODES + 1];
__device__ int   d_cursor[N_NODES];
__device__ int   d_ssrc[N_EDGES];
__device__ int   d_partial[256];

__device__ __forceinline__ float lrelu(float x) { return x > 0.f ? x : NEG_SLOPE * x; }

// ---------------- init ----------------
__global__ void zero_small_kernel() {
    int i = blockIdx.x * blockDim.x + threadIdx.x;
    if (i < 6 * 256) d_stats[i] = 0.f;
    if (i < 5 * FDIM) d_bp[i] = 0.f;
    if (i < N_GRAPHS * FDIM) d_g[i] = 0.f;
    if (i < N_NODES) d_deg[i] = 0;
}

// ---------------- CSR build ----------------
__global__ void csr_count_kernel(const int* __restrict__ edst) {
    int e = blockIdx.x * blockDim.x + threadIdx.x;
    if (e < N_EDGES) atomicAdd(&d_deg[edst[e]], 1);
}

#define SCAN_NB 256
#define SCAN_CHUNK ((N_NODES + SCAN_NB - 1) / SCAN_NB)   // 196

__global__ void scan1_kernel() {
    __shared__ int sred[256];
    int b = blockIdx.x, t = threadIdx.x;
    int idx = b * SCAN_CHUNK + t;
    int v = (t < SCAN_CHUNK && idx < N_NODES) ? d_deg[idx] : 0;
    sred[t] = v;
    __syncthreads();
    for (int off = 128; off > 0; off >>= 1) {
        if (t < off) sred[t] += sred[t + off];
        __syncthreads();
    }
    if (t == 0) d_partial[b] = sred[0];
}

// parallel exclusive scan over the 256 block partials
__global__ void scan2_kernel() {
    __shared__ int sm[256];
    int t = threadIdx.x;
    int v = d_partial[t];
    sm[t] = v;
    __syncthreads();
    for (int off = 1; off < 256; off <<= 1) {
        int x = (t >= off) ? sm[t - off] : 0;
        __syncthreads();
        sm[t] += x;
        __syncthreads();
    }
    d_partial[t] = sm[t] - v;   // exclusive
}

// parallel per-chunk exclusive scan (Hillis-Steele over 256 lanes)
__global__ void scan3_kernel() {
    __shared__ int sm[256];
    int b = blockIdx.x, t = threadIdx.x;
    int i0 = b * SCAN_CHUNK;
    int idx = i0 + t;
    int v = (t < SCAN_CHUNK && idx < N_NODES) ? d_deg[idx] : 0;
    sm[t] = v;
    __syncthreads();
    for (int off = 1; off < 256; off <<= 1) {
        int x = (t >= off) ? sm[t - off] : 0;
        __syncthreads();
        sm[t] += x;
        __syncthreads();
    }
    int base = d_partial[b];
    if (t < SCAN_CHUNK && idx < N_NODES) {
        int st = base + sm[t] - v;     // exclusive
        d_start[idx] = st;
        d_cursor[idx] = st;
        if (idx == N_NODES - 1) d_start[N_NODES] = base + sm[t];
    }
}

__global__ void csr_scatter_kernel(const int* __restrict__ esrc,
                                   const int* __restrict__ edst) {
    int e = blockIdx.x * blockDim.x + threadIdx.x;
    if (e >= N_EDGES) return;
    int pos = atomicAdd(&d_cursor[edst[e]], 1);
    d_ssrc[pos] = esrc[e];
}

// ---------------- per-column stats ----------------
__global__ void colstats_kernel(const float* __restrict__ A, int rows, int slot) {
    int t = threadIdx.x;
    int per = (rows + gridDim.x - 1) / gridDim.x;
    int r0 = blockIdx.x * per;
    int r1 = min(r0 + per, rows);
    float s = 0.f, q = 0.f;
    for (int r = r0; r < r1; r++) {
        float v = A[(size_t)r * FDIM + t];
        s += v; q += v * v;
    }
    atomicAdd(&d_stats[slot * 256 + t], s);
    atomicAdd(&d_stats[slot * 256 + FDIM + t], q);
}

__global__ void colstats_g_kernel(int slot) {
    int t = threadIdx.x;
    int per = (N_GRAPHS + gridDim.x - 1) / gridDim.x;
    int r0 = blockIdx.x * per;
    int r1 = min(r0 + per, N_GRAPHS);
    float s = 0.f, q = 0.f;
    for (int r = r0; r < r1; r++) {
        float v = d_g[r * FDIM + t];
        s += v; q += v * v;
    }
    atomicAdd(&d_stats[slot * 256 + t], s);
    atomicAdd(&d_stats[slot * 256 + FDIM + t], q);
}

// ---------------- fold BN into weight (k-parallel: 128 blocks) -------------
// block k, thread t: d_wp[k,t] = sc_k * W[k,t];  d_bp[bias_slot] += sh_k * W[k,:]
__global__ void transform_kernel(const float* __restrict__ W,
                                 const float* __restrict__ g,
                                 const float* __restrict__ b,
                                 const float* __restrict__ extra_bias,
                                 float inv_n, int stats_slot, int bias_slot) {
    int k = blockIdx.x, t = threadIdx.x;
    float mean = d_stats[stats_slot * 256 + k] * inv_n;
    float var  = d_stats[stats_slot * 256 + FDIM + k] * inv_n - mean * mean;
    float sc = g[k] * rsqrtf(var + BN_EPS);
    float sh = b[k] - mean * sc;
    float w = W[k * FDIM + t];
    d_wp[k * FDIM + t] = sc * w;
    float contrib = sh * w;
    if (k == 0 && extra_bias) contrib += extra_bias[t];
    atomicAdd(&d_bp[bias_slot * FDIM + t], contrib);
}

// ---------------- 128x128-tile SGEMM, 8x8 per thread, fused epilogues ------
__global__ void __launch_bounds__(256, 2)
gemm_kernel(const float* __restrict__ Aext, int asel, int M, int csel,
            const float* __restrict__ a_src, const float* __restrict__ a_dst,
            int flags, int stats_slot, int bias_slot) {
    __shared__ float As[16 * 132];     // [k][m], padded row stride 132
    __shared__ float Bs[16 * 128];     // [k][n]
    __shared__ float sstat[256];
    const float* A = (asel == 0) ? Aext
                    : (asel == 1 ? (const float*)d_h : (const float*)d_g);
    float* C = (csel == 1) ? (float*)d_h : (float*)d_hw;
    const float* bp = d_bp + bias_slot * FDIM;

    int tid = threadIdx.x;
    int tn = tid & 15, tm = tid >> 4;
    int row_base = blockIdx.x * 128;

    int ar0 = tid >> 2, akq = tid & 3;
    int ar1 = (tid + 256) >> 2;
    size_t grow0 = (size_t)min(row_base + ar0, M - 1);
    size_t grow1 = (size_t)min(row_base + ar1, M - 1);
    const float4* A4 = (const float4*)A;
    const float4* W4 = (const float4*)d_wp;

    float acc[8][8];
#pragma unroll
    for (int i = 0; i < 8; i++)
#pragma unroll
        for (int j = 0; j < 8; j++) acc[i][j] = 0.f;

    float4 pa0 = __ldg(&A4[grow0 * 32 + akq]);
    float4 pa1 = __ldg(&A4[grow1 * 32 + akq]);
    float4 pb0 = W4[tid];
    float4 pb1 = W4[tid + 256];

    for (int s = 0; s < 8; s++) {
        As[(akq * 4 + 0) * 132 + ar0] = pa0.x;
        As[(akq * 4 + 1) * 132 + ar0] = pa0.y;
        As[(akq * 4 + 2) * 132 + ar0] = pa0.z;
        As[(akq * 4 + 3) * 132 + ar0] = pa0.w;
        As[(akq * 4 + 0) * 132 + ar1] = pa1.x;
        As[(akq * 4 + 1) * 132 + ar1] = pa1.y;
        As[(akq * 4 + 2) * 132 + ar1] = pa1.z;
        As[(akq * 4 + 3) * 132 + ar1] = pa1.w;
        ((float4*)Bs)[tid] = pb0;
        ((float4*)Bs)[tid + 256] = pb1;
        __syncthreads();
        if (s < 7) {
            pa0 = __ldg(&A4[grow0 * 32 + (s + 1) * 4 + akq]);
            pa1 = __ldg(&A4[grow1 * 32 + (s + 1) * 4 + akq]);
            pb0 = W4[(s + 1) * 512 + tid];
            pb1 = W4[(s + 1) * 512 + tid + 256];
        }
#pragma unroll
        for (int k = 0; k < 16; k++) {
            float4 a0 = *(float4*)&As[k * 132 + tm * 4];
            float4 a1 = *(float4*)&As[k * 132 + tm * 4 + 64];
            float4 b0 = *(float4*)&Bs[k * 128 + tn * 4];
            float4 b1 = *(float4*)&Bs[k * 128 + tn * 4 + 64];
            float av[8] = {a0.x, a0.y, a0.z, a0.w, a1.x, a1.y, a1.z, a1.w};
            float bv[8] = {b0.x, b0.y, b0.z, b0.w, b1.x, b1.y, b1.z, b1.w};
#pragma unroll
            for (int i = 0; i < 8; i++)
#pragma unroll
                for (int j = 0; j < 8; j++)
                    acc[i][j] += av[i] * bv[j];
        }
        __syncthreads();
    }

    // ---- epilogue ----
    float bpv[8];
    *(float4*)&bpv[0] = *(const float4*)&bp[tn * 4];
    *(float4*)&bpv[4] = *(const float4*)&bp[tn * 4 + 64];
    float asl[8], adl[8];
    if (flags & GF_ALPHA) {
        *(float4*)&asl[0] = *(const float4*)&a_src[tn * 4];
        *(float4*)&asl[4] = *(const float4*)&a_src[tn * 4 + 64];
        *(float4*)&adl[0] = *(const float4*)&a_dst[tn * 4];
        *(float4*)&adl[4] = *(const float4*)&a_dst[tn * 4 + 64];
    }
    if (flags & GF_STATS) sstat[tid] = 0.f;

    float ss[8], sq[8];
#pragma unroll
    for (int j = 0; j < 8; j++) { ss[j] = 0.f; sq[j] = 0.f; }

#pragma unroll
    for (int i = 0; i < 8; i++) {
        int m_local = (i < 4) ? (tm * 4 + i) : (tm * 4 + 64 + i - 4);
        int row = row_base + m_local;
        bool ok = (row < M);
        float v[8];
#pragma unroll
        for (int j = 0; j < 8; j++) v[j] = acc[i][j] + bpv[j];
        if (flags & GF_ALPHA) {
            float pl = v[0]*asl[0] + v[1]*asl[1] + v[2]*asl[2] + v[3]*asl[3];
            float ph = v[4]*asl[4] + v[5]*asl[5] + v[6]*asl[6] + v[7]*asl[7];
            float ql = v[0]*adl[0] + v[1]*adl[1] + v[2]*adl[2] + v[3]*adl[3];
            float qh = v[4]*adl[4] + v[5]*adl[5] + v[6]*adl[6] + v[7]*adl[7];
#pragma unroll
            for (int off = 4; off > 0; off >>= 1) {
                pl += __shfl_down_sync(0xffffffffu, pl, off, 8);
                ph += __shfl_down_sync(0xffffffffu, ph, off, 8);
                ql += __shfl_down_sync(0xffffffffu, ql, off, 8);
                qh += __shfl_down_sync(0xffffffffu, qh, off, 8);
            }
            if (ok && (tn & 7) == 0) {
                int hbase = tn >> 3;            // 0 or 1
                d_als[row * HEADS + hbase]     = pl;
                d_als[row * HEADS + hbase + 2] = ph;
                d_ald[row * HEADS + hbase]     = ql;
                d_ald[row * HEADS + hbase + 2] = qh;
            }
        }
        if (flags & GF_RELU) {
#pragma unroll
            for (int j = 0; j < 8; j++) v[j] = fmaxf(v[j], 0.f);
        }
        if (ok) {
            *(float4*)&C[(size_t)row * FDIM + tn * 4]      = *(float4*)&v[0];
            *(float4*)&C[(size_t)row * FDIM + tn * 4 + 64] = *(float4*)&v[4];
#pragma unroll
            for (int j = 0; j < 8; j++) { ss[j] += v[j]; sq[j] += v[j] * v[j]; }
        }
    }

    if (flags & GF_STATS) {
        __syncthreads();
#pragma unroll
        for (int j = 0; j < 8; j++) {
            int col = (j < 4) ? (tn * 4 + j) : (tn * 4 + 64 + j - 4);
            atomicAdd(&sstat[col], ss[j]);
            atomicAdd(&sstat[128 + col], sq[j]);
        }
        __syncthreads();
        atomicAdd(&d_stats[stats_slot * 256 + tid], sstat[tid]);
    }
}

// ---------------- fused GAT aggregation (warp per dst node) ----------------
// out = (sum_e exp(l_e) * hw[src_e]) / (sum_e exp(l_e) + eps) — max shift cancels
// fuse_pool: last conv — skip d_h write, accumulate into d_g[batch[n]] directly
__global__ void __launch_bounds__(256)
agg_kernel(const float* __restrict__ bias, int do_stats, int stats_slot,
           int fuse_pool, const int* __restrict__ batch) {
    __shared__ float sred[256];
    int tid = threadIdx.x;
    int lane = tid & 31;
    int n = blockIdx.x * 8 + (tid >> 5);
    int head = lane >> 3;

    float ss0 = 0, ss1 = 0, ss2 = 0, ss3 = 0;
    float sq0 = 0, sq1 = 0, sq2 = 0, sq3 = 0;

    if (n < N_NODES) {
        float aldv = d_ald[n * HEADS + head];
        float e = __expf(lrelu(d_als[n * HEADS + head] + aldv));   // self-loop
        float4 hv = *(const float4*)&d_hw[(size_t)n * FDIM + lane * 4];
        float4 acc = make_float4(e * hv.x, e * hv.y, e * hv.z, e * hv.w);
        float S = e;

        int p = d_start[n];
        int pend = d_start[n + 1];
        // 8-deep pipelined main loop
        for (; p + 7 < pend; p += 8) {
            int si[8];
#pragma unroll
            for (int u = 0; u < 8; u++) si[u] = __ldg(&d_ssrc[p + u]);
            float4 hh[8];
#pragma unroll
            for (int u = 0; u < 8; u++)
                hh[u] = __ldg((const float4*)&d_hw[(size_t)si[u] * FDIM + lane * 4]);
            float aa[8];
#pragma unroll
            for (int u = 0; u < 8; u++) aa[u] = __ldg(&d_als[si[u] * HEADS + head]);
#pragma unroll
            for (int u = 0; u < 8; u++) {
                float ee = __expf(lrelu(aa[u] + aldv));
                S += ee;
                acc.x += ee * hh[u].x; acc.y += ee * hh[u].y;
                acc.z += ee * hh[u].z; acc.w += ee * hh[u].w;
            }
        }
        for (; p + 3 < pend; p += 4) {
            int s0 = __ldg(&d_ssrc[p + 0]);
            int s1 = __ldg(&d_ssrc[p + 1]);
            int s2 = __ldg(&d_ssrc[p + 2]);
            int s3 = __ldg(&d_ssrc[p + 3]);
            float4 h0 = __ldg((const float4*)&d_hw[(size_t)s0 * FDIM + lane * 4]);
            float4 h1 = __ldg((const float4*)&d_hw[(size_t)s1 * FDIM + lane * 4]);
            float4 h2 = __ldg((const float4*)&d_hw[(size_t)s2 * FDIM + lane * 4]);
            float4 h3 = __ldg((const float4*)&d_hw[(size_t)s3 * FDIM + lane * 4]);
            float a0 = __ldg(&d_als[s0 * HEADS + head]);
            float a1 = __ldg(&d_als[s1 * HEADS + head]);
            float a2 = __ldg(&d_als[s2 * HEADS + head]);
            float a3 = __ldg(&d_als[s3 * HEADS + head]);
            float e0 = __expf(lrelu(a0 + aldv));
            float e1 = __expf(lrelu(a1 + aldv));
            float e2 = __expf(lrelu(a2 + aldv));
            float e3 = __expf(lrelu(a3 + aldv));
            S += (e0 + e1) + (e2 + e3);
            acc.x += e0 * h0.x + e1 * h1.x + e2 * h2.x + e3 * h3.x;
            acc.y += e0 * h0.y + e1 * h1.y + e2 * h2.y + e3 * h3.y;
            acc.z += e0 * h0.z + e1 * h1.z + e2 * h2.z + e3 * h3.z;
            acc.w += e0 * h0.w + e1 * h1.w + e2 * h2.w + e3 * h3.w;
        }
        for (; p < pend; p++) {
            int s = __ldg(&d_ssrc[p]);
            float av = __ldg(&d_als[s * HEADS + head]);
            float4 h4 = __ldg((const float4*)&d_hw[(size_t)s * FDIM + lane * 4]);
            float ee = __expf(lrelu(av + aldv));
            S += ee;
            acc.x += ee * h4.x; acc.y += ee * h4.y;
            acc.z += ee * h4.z; acc.w += ee * h4.w;
        }
        float inv = 1.0f / (S + 1e-16f);
        float4 bv = *(const float4*)&bias[lane * 4];
        float4 v;
        v.x = fmaxf(acc.x * inv + bv.x, 0.f);
        v.y = fmaxf(acc.y * inv + bv.y, 0.f);
        v.z = fmaxf(acc.z * inv + bv.z, 0.f);
        v.w = fmaxf(acc.w * inv + bv.w, 0.f);
        if (fuse_pool) {
            int gi = __ldg(&batch[n]);
            atomicAdd((float4*)&d_g[gi * FDIM + lane * 4], v);
        } else {
            *(float4*)&d_h[(size_t)n * FDIM + lane * 4] = v;
        }
        ss0 = v.x; ss1 = v.y; ss2 = v.z; ss3 = v.w;
        sq0 = v.x * v.x; sq1 = v.y * v.y; sq2 = v.z * v.z; sq3 = v.w * v.w;
    }

    if (do_stats) {
        sred[tid] = 0.f;
        __syncthreads();
        atomicAdd(&sred[4 * lane + 0], ss0); atomicAdd(&sred[4 * lane + 1], ss1);
        atomicAdd(&sred[4 * lane + 2], ss2); atomicAdd(&sred[4 * lane + 3], ss3);
        atomicAdd(&sred[128 + 4 * lane + 0], sq0); atomicAdd(&sred[128 + 4 * lane + 1], sq1);
        atomicAdd(&sred[128 + 4 * lane + 2], sq2); atomicAdd(&sred[128 + 4 * lane + 3], sq3);
        __syncthreads();
        atomicAdd(&d_stats[stats_slot * 256 + tid], sred[tid]);
    }
}

// ---------------- BN(g2) + classifier + log_softmax ----------------
__global__ void classifier_kernel(const float* __restrict__ bnh_g,
                                  const float* __restrict__ bnh_b,
                                  const float* __restrict__ cls_w,
                                  const float* __restrict__ cls_b,
                                  float* __restrict__ out, int stats_slot) {
    int gi = blockIdx.x, t = threadIdx.x;
    float mean = d_stats[stats_slot * 256 + t] * (1.0f / N_GRAPHS);
    float var  = d_stats[stats_slot * 256 + FDIM + t] * (1.0f / N_GRAPHS) - mean * mean;
    float v = (d_hw[gi * FDIM + t] - mean) * rsqrtf(var + BN_EPS) * bnh_g[t] + bnh_b[t];
    __shared__ float sh[128];
    __shared__ float z[16];
    for (int c = 0; c < NCLS; c++) {
        sh[t] = v * cls_w[t * NCLS + c];
        __syncthreads();
        if (t < 64) sh[t] += sh[t + 64];
        __syncthreads();
        if (t < 32) {
            float s = sh[t] + sh[t + 32];
#pragma unroll
            for (int off = 16; off > 0; off >>= 1)
                s += __shfl_down_sync(0xffffffffu, s, off);
            if (t == 0) z[c] = s + cls_b[c];
        }
        __syncthreads();
    }
    if (t == 0) {
        float m = z[0];
        for (int c = 1; c < NCLS; c++) m = fmaxf(m, z[c]);
        float se = 0.f;
        for (int c = 0; c < NCLS; c++) se += expf(z[c] - m);
        float lse = m + logf(se);
        for (int c = 0; c < NCLS; c++) out[gi * NCLS + c] = z[c] - lse;
    }
}

// ---------------- launch ----------------
extern "C" void kernel_launch(void* const* d_in, const int* in_sizes, int n_in,
                              void* d_out, int out_size) {
    const float* x        = (const float*)d_in[0];
    const int*   eidx     = (const int*)d_in[1];
    const int*   batch    = (const int*)d_in[2];
    const float* w_feat   = (const float*)d_in[3];
    const float* bnf_g    = (const float*)d_in[4];
    const float* bnf_b    = (const float*)d_in[5];
    const float* bnc_g    = (const float*)d_in[6];
    const float* bnc_b    = (const float*)d_in[7];
    const float* gat_w    = (const float*)d_in[8];
    const float* gat_asrc = (const float*)d_in[9];
    const float* gat_adst = (const float*)d_in[10];
    const float* gat_b    = (const float*)d_in[11];
    const float* bnfc_g   = (const float*)d_in[12];
    const float* bnfc_b   = (const float*)d_in[13];
    const float* lin_w    = (const float*)d_in[14];
    const float* lin_b    = (const float*)d_in[15];
    const float* bnh_g    = (const float*)d_in[16];
    const float* bnh_b    = (const float*)d_in[17];
    const float* cls_w    = (const float*)d_in[18];
    const float* cls_b    = (const float*)d_in[19];
    float* out = (float*)d_out;

    const int* esrc = eidx;
    const int* edst = eidx + N_EDGES;

    const int gemm_blocks = (N_NODES + 127) / 128;
    const int edge_blocks = (N_EDGES + 255) / 256;
    const int agg_blocks  = (N_NODES + 7) / 8;

    // init + CSR build (reused for all 3 convs)
    zero_small_kernel<<<(N_NODES + 255) / 256, 256>>>();
    csr_count_kernel<<<edge_blocks, 256>>>(edst);
    scan1_kernel<<<SCAN_NB, 256>>>();
    scan2_kernel<<<1, 256>>>();
    scan3_kernel<<<SCAN_NB, 256>>>();
    csr_scatter_kernel<<<edge_blocks, 256>>>(esrc, edst);

    // stats slots: 0=x, 1=h(pre-conv0), 2=h(pre-conv1), 3=h(pre-conv2),
    //              4=pooled g, 5=g2. bias slots 0..4 per transform instance.
    colstats_kernel<<<200, 128>>>(x, N_NODES, 0);
    transform_kernel<<<128, 128>>>(w_feat, bnf_g, bnf_b, nullptr,
                                   1.0f / N_NODES, 0, 0);
    gemm_kernel<<<gemm_blocks, 256>>>(x, 0, N_NODES, 1, nullptr, nullptr,
                                      GF_RELU | GF_STATS, 1, 0);

    for (int i = 0; i < 3; i++) {
        transform_kernel<<<128, 128>>>(gat_w + i * FDIM * FDIM,
                                       bnc_g + i * FDIM, bnc_b + i * FDIM,
                                       nullptr, 1.0f / N_NODES, 1 + i, 1 + i);
        gemm_kernel<<<gemm_blocks, 256>>>(nullptr, 1, N_NODES, 2,
                                          gat_asrc + i * HEADS * DHEAD,
                                          gat_adst + i * HEADS * DHEAD,
                                          GF_ALPHA, 0, 1 + i);
        agg_kernel<<<agg_blocks, 256>>>(gat_b + i * FDIM,
                                        (i < 2) ? 1 : 0, 2 + i,
                                        (i == 2) ? 1 : 0, batch);
    }

    colstats_g_kernel<<<8, 128>>>(4);
    transform_kernel<<<128, 128>>>(lin_w, bnfc_g, bnfc_b, lin_b,
                                   1.0f / N_GRAPHS, 4, 4);
    gemm_kernel<<<(N_GRAPHS + 127) / 128, 256>>>(nullptr, 2, N_GRAPHS, 2,
                                                 nullptr, nullptr,
                                                 GF_RELU | GF_STATS, 5, 4);
    classifier_kernel<<<N_GRAPHS, 128>>>(bnh_g, bnh_b, cls_w, cls_b, out, 5);
}